// round 1
// baseline (speedup 1.0000x reference)
#include <cuda_runtime.h>
#include <math.h>

// Problem constants (shapes fixed by the dataset; N derived from in_sizes).
#define VV 2
#define KK 8
#define DD 128
#define DAUG 129          // D + 1 (augmented column folds u = M*mu)
#define DAP 136           // padded to 17 chunks of 8
#define TN 128            // points per block tile
#define LOG2PI_F 1.8378770664093453f

// Scratch (no cudaMalloc allowed): W[v][k][j][i] = M'_k[i][j], j in [0,DAP)
__device__ float g_W[VV * KK * DAP * DD];
__device__ float g_logc[VV * KK];

// ---------------------------------------------------------------------------
// packed f32x2 FMA helpers (ptxas will not auto-fuse; must come from PTX)
// ---------------------------------------------------------------------------
__device__ __forceinline__ unsigned long long dup2(float x) {
    unsigned long long r;
    asm("mov.b64 %0, {%1, %1};" : "=l"(r) : "r"(__float_as_uint(x)));
    return r;
}
#define FFMA2(d, a, b) asm("fma.rn.f32x2 %0, %1, %2, %0;" : "+l"(d) : "l"(a), "l"(b))

// ---------------------------------------------------------------------------
// init: zero the two scalar accumulator slots
// ---------------------------------------------------------------------------
__global__ void init_kernel(float* __restrict__ out, int Npts) {
    size_t base = (size_t)4 * Npts;
    out[base] = 0.0f;
    out[base + 1] = 0.0f;
}

// ---------------------------------------------------------------------------
// setup: per (v,k) Cholesky of sigma+1e-6*I, M = L^{-1}, u = M*mu, log-consts,
// penalty accumulation. One block per (v,k): 16 blocks, 128 threads.
// Dynamic smem: A[128][129] + M[128][129] + red[128] + mus[128]
// ---------------------------------------------------------------------------
__global__ void setup_kernel(const float* __restrict__ phi,
                             const float* __restrict__ mu,
                             const float* __restrict__ sigma,
                             float* __restrict__ out, int Npts) {
    extern __shared__ float sm[];
    float (*A)[DD + 1] = (float (*)[DD + 1])sm;
    float (*M)[DD + 1] = (float (*)[DD + 1])(sm + DD * (DD + 1));
    float* red = sm + 2 * DD * (DD + 1);
    float* mus = red + DD;

    const int t = threadIdx.x;                 // 0..127
    const int v = blockIdx.x / KK;
    const int k = blockIdx.x % KK;
    const float* S = sigma + (size_t)(v * KK + k) * DD * DD;

    // load sigma (column t of each row), coalesced
    for (int r = 0; r < DD; r++) A[r][t] = S[r * DD + t];
    __syncthreads();

    // diagonal eps + penalty contribution
    float dg = A[t][t] + 1e-6f;
    A[t][t] = dg;
    red[t] = 1.0f / (dg + 1e-12f);
    __syncthreads();
    for (int s = 64; s > 0; s >>= 1) {
        if (t < s) red[t] += red[t + s];
        __syncthreads();
    }
    if (t == 0) atomicAdd(&out[(size_t)4 * Npts + 1], red[0]);
    __syncthreads();

    // right-looking Cholesky (lower), in place
    for (int j = 0; j < DD; j++) {
        if (t == j) A[j][j] = sqrtf(A[j][j]);
        __syncthreads();
        float Ljj = A[j][j];
        float lij = 0.0f;
        if (t > j) {
            lij = A[t][j] / Ljj;
            A[t][j] = lij;
        }
        __syncthreads();
        if (t > j) {
            for (int l = j + 1; l <= t; l++)
                A[t][l] = fmaf(-lij, A[l][j], A[t][l]);
        }
        __syncthreads();
    }

    // logdet = 2 * sum log(L_ii), with det clip matching reference
    red[t] = logf(A[t][t]);
    __syncthreads();
    for (int s = 64; s > 0; s >>= 1) {
        if (t < s) red[t] += red[t + s];
        __syncthreads();
    }
    float logdet = fmaxf(2.0f * red[0], logf(1e-6f));
    __syncthreads();

    // triangular inverse M = L^{-1}; thread t owns column t (column-private)
    for (int r = 0; r < DD; r++) M[r][t] = 0.0f;
    __syncthreads();
    const int c = t;
    for (int j = 0; j < DD; j++) {
        float s = 0.0f;
        for (int i = 0; i < j; i++) s = fmaf(A[j][i], M[i][c], s);
        if (j >= c) M[j][c] = (((j == c) ? 1.0f : 0.0f) - s) / A[j][j];
    }
    __syncthreads();

    // u = M * mu (thread t = row t)
    mus[t] = mu[(size_t)(v * KK + k) * DD + t];
    __syncthreads();
    float u = 0.0f;
    for (int j = 0; j < DD; j++) u = fmaf(M[t][j], mus[j], u);

    // write W: W[j][i] = M[i][j] for j<128; W[128][i] = -u_i; rest 0
    float* Wp = g_W + (size_t)(v * KK + k) * DAP * DD;
    for (int j = 0; j < DD; j++) Wp[j * DD + t] = M[t][j];
    Wp[DD * DD + t] = -u;
    for (int j = DAUG; j < DAP; j++) Wp[j * DD + t] = 0.0f;

    if (t == 0) {
        float pm = -3.0e38f;
        for (int i = 0; i < KK; i++) pm = fmaxf(pm, phi[v * KK + i]);
        float se = 0.0f;
        for (int i = 0; i < KK; i++) se += expf(phi[v * KK + i] - pm);
        float logpi = phi[v * KK + k] - pm - logf(se);
        g_logc[v * KK + k] = logpi - 0.5f * (float)DD * LOG2PI_F - 0.5f * logdet;
    }
}

// ---------------------------------------------------------------------------
// main: per view, per 128-point tile: Y = Z' * W_k, maha = rowsumsq(Y),
// fused logsumexp over k -> energies. Register-tiled 8x8, f32x2 FFMA.
// Dynamic smem: Zs[136][132] + Bs[8][128] + Ssm[128][8]
// ---------------------------------------------------------------------------
__global__ void __launch_bounds__(256, 2)
main_kernel(const float* __restrict__ z, float* __restrict__ out,
            int Npts, int bpv) {
    extern __shared__ float sm[];
    float* Zs = sm;                       // [DAP][132], kk-major, padded
    float* Bs = Zs + DAP * 132;           // [8][128]  W chunk
    float* Ssm = Bs + 8 * DD;             // [128][8]  maha per (pt, k)

    const int tid = threadIdx.x;
    const int v = blockIdx.x / bpv;
    const int nb = blockIdx.x - v * bpv;
    const int n0 = nb * TN;

    // stage Z tile transposed (+ augmented one-row + zero pad)
    for (int idx = tid; idx < TN * DD; idx += 256) {
        int p = idx >> 7;
        int kk = idx & 127;
        int n = n0 + p;
        float val = (n < Npts) ? z[((size_t)v * Npts + n) * DD + kk] : 0.0f;
        Zs[kk * 132 + p] = val;
    }
    for (int p = tid; p < TN; p += 256) {
        Zs[128 * 132 + p] = ((n0 + p) < Npts) ? 1.0f : 0.0f;
        for (int j = DAUG; j < DAP; j++) Zs[j * 132 + p] = 0.0f;
    }
    __syncthreads();

    const int tx = tid & 15;              // column group (8 cols each)
    const int ty = tid >> 4;              // point group  (8 pts each)
    const float* Wbase = g_W + (size_t)v * KK * DAP * DD;

    for (int k = 0; k < KK; k++) {
        unsigned long long acc[8][4];
#pragma unroll
        for (int r = 0; r < 8; r++)
#pragma unroll
            for (int cp = 0; cp < 4; cp++) acc[r][cp] = 0ULL;

        const float* Wk = Wbase + (size_t)k * DAP * DD;
        for (int ch = 0; ch < 17; ch++) {
#pragma unroll
            for (int u2 = 0; u2 < 4; u2++) {
                int j = tid + u2 * 256;   // 0..1023
                Bs[j] = Wk[ch * 8 * DD + j];
            }
            __syncthreads();
#pragma unroll
            for (int kk8 = 0; kk8 < 8; kk8++) {
                const int kkg = ch * 8 + kk8;
                const float4* za = (const float4*)(Zs + kkg * 132 + ty * 8);
                float4 a0 = za[0];
                float4 a1 = za[1];
                unsigned long long zz[8];
                zz[0] = dup2(a0.x); zz[1] = dup2(a0.y);
                zz[2] = dup2(a0.z); zz[3] = dup2(a0.w);
                zz[4] = dup2(a1.x); zz[5] = dup2(a1.y);
                zz[6] = dup2(a1.z); zz[7] = dup2(a1.w);
                const ulonglong2* bb = (const ulonglong2*)(Bs + kk8 * DD + tx * 8);
                ulonglong2 b0 = bb[0];
                ulonglong2 b1 = bb[1];
                unsigned long long rb[4] = {b0.x, b0.y, b1.x, b1.y};
#pragma unroll
                for (int r = 0; r < 8; r++)
#pragma unroll
                    for (int cp = 0; cp < 4; cp++)
                        FFMA2(acc[r][cp], zz[r], rb[cp]);
            }
            __syncthreads();
        }

        // epilogue: sum of squares over this thread's 8 cols, then 16-lane reduce
#pragma unroll
        for (int r = 0; r < 8; r++) {
            float s = 0.0f;
#pragma unroll
            for (int cp = 0; cp < 4; cp++) {
                float lo = __uint_as_float((unsigned int)acc[r][cp]);
                float hi = __uint_as_float((unsigned int)(acc[r][cp] >> 32));
                s = fmaf(lo, lo, s);
                s = fmaf(hi, hi, s);
            }
            s += __shfl_xor_sync(0xffffffffu, s, 1);
            s += __shfl_xor_sync(0xffffffffu, s, 2);
            s += __shfl_xor_sync(0xffffffffu, s, 4);
            s += __shfl_xor_sync(0xffffffffu, s, 8);
            if (tx == 0) Ssm[(ty * 8 + r) * 8 + k] = s;
        }
    }
    __syncthreads();

    // per-point logsumexp over k -> energy
    if (tid < TN) {
        int n = n0 + tid;
        if (n < Npts) {
            float lp[KK];
            float m = -3.0e38f;
#pragma unroll
            for (int k = 0; k < KK; k++) {
                lp[k] = fmaf(-0.5f, Ssm[tid * 8 + k], g_logc[v * KK + k]);
                m = fmaxf(m, lp[k]);
            }
            float se = 0.0f;
#pragma unroll
            for (int k = 0; k < KK; k++) se += expf(lp[k] - m);
            out[(size_t)n * VV + v] = -(m + logf(se));
        }
    }
}

// ---------------------------------------------------------------------------
// finalize: weights = softmax(-energies/tau) over views, total_energies
// ---------------------------------------------------------------------------
__global__ void finalize_kernel(float* __restrict__ out, int Npts) {
    int n = blockIdx.x * blockDim.x + threadIdx.x;
    float esum = 0.0f;
    if (n < Npts) {
        float e0 = out[2 * n];
        float e1 = out[2 * n + 1];
        float m = fminf(e0, e1);
        float a = expf(m - e0);
        float b = expf(m - e1);
        float inv = 1.0f / (a + b);
        size_t wb = (size_t)2 * Npts;
        out[wb + 2 * n] = a * inv;
        out[wb + 2 * n + 1] = b * inv;
        esum = e0 + e1;
    }
    __shared__ float wsum[8];
    for (int o = 16; o; o >>= 1) esum += __shfl_xor_sync(0xffffffffu, esum, o);
    if ((threadIdx.x & 31) == 0) wsum[threadIdx.x >> 5] = esum;
    __syncthreads();
    if (threadIdx.x < 8) {
        float x = wsum[threadIdx.x];
        for (int o = 4; o; o >>= 1) x += __shfl_xor_sync(0x000000ffu, x, o);
        if (threadIdx.x == 0) atomicAdd(&out[(size_t)4 * Npts], x);
    }
}

// ---------------------------------------------------------------------------
extern "C" void kernel_launch(void* const* d_in, const int* in_sizes, int n_in,
                              void* d_out, int out_size) {
    (void)n_in;
    (void)out_size;
    const float* z = (const float*)d_in[0];
    const float* phi = (const float*)d_in[1];
    const float* mu = (const float*)d_in[2];
    const float* sigma = (const float*)d_in[3];
    float* out = (float*)d_out;

    const int Npts = in_sizes[0] / (VV * DD);   // 100000

    const int SETUP_SMEM = (2 * DD * (DD + 1) + 2 * DD) * (int)sizeof(float); // 133120
    const int MAIN_SMEM = (DAP * 132 + 8 * DD + TN * KK) * (int)sizeof(float); // 80000

    cudaFuncSetAttribute(setup_kernel,
                         cudaFuncAttributeMaxDynamicSharedMemorySize, SETUP_SMEM);
    cudaFuncSetAttribute(main_kernel,
                         cudaFuncAttributeMaxDynamicSharedMemorySize, MAIN_SMEM);

    init_kernel<<<1, 1>>>(out, Npts);
    setup_kernel<<<VV * KK, DD, SETUP_SMEM>>>(phi, mu, sigma, out, Npts);

    const int bpv = (Npts + TN - 1) / TN;
    main_kernel<<<VV * bpv, 256, MAIN_SMEM>>>(z, out, Npts, bpv);

    finalize_kernel<<<(Npts + 255) / 256, 256>>>(out, Npts);
}

// round 3
// speedup vs baseline: 2.1803x; 2.1803x over previous
#include <cuda_runtime.h>
#include <cuda_bf16.h>
#include <math.h>
#include <stdint.h>

#define VV 2
#define KK 8
#define DD 128
#define TN 128
#define LOG2PI_F 1.8378770664093453f

// B fragments, frag-packed per (v,comp): [hl][kb][w][nt][lane][reg] u32
// 16384 u32 per comp -> 1 MB total (L2-resident).
__device__ uint32_t g_Bfrag[VV * KK * 16384];
__device__ float g_u[VV * KK * DD];
__device__ float g_logc[VV * KK];

__device__ __forceinline__ void split_bf16(float x, unsigned short& h, unsigned short& l) {
    __nv_bfloat16 hb = __float2bfloat16(x);
    float r = x - __bfloat162float(hb);
    __nv_bfloat16 lb = __float2bfloat16(r);
    h = __bfloat16_as_ushort(hb);
    l = __bfloat16_as_ushort(lb);
}

// m16n8k16 bf16 MMA, f32 accumulate (PTX ISA 8.0, valid on compute_103)
#define MMA16816(c, a, b)                                                      \
    asm volatile(                                                              \
        "mma.sync.aligned.m16n8k16.row.col.f32.bf16.bf16.f32 "                 \
        "{%0,%1,%2,%3}, {%4,%5,%6,%7}, {%8,%9}, {%0,%1,%2,%3};"                \
        : "+f"((c)[0]), "+f"((c)[1]), "+f"((c)[2]), "+f"((c)[3])               \
        : "r"((a)[0]), "r"((a)[1]), "r"((a)[2]), "r"((a)[3]),                  \
          "r"((b).x), "r"((b).y))

// ---------------------------------------------------------------------------
__global__ void init_kernel(float* __restrict__ out, int Npts) {
    size_t base = (size_t)4 * Npts;
    out[base] = 0.0f;
    out[base + 1] = 0.0f;
}

// ---------------------------------------------------------------------------
// setup: per (v,k) Cholesky of sigma+1e-6 I, M=L^-1, u=M*mu, penalty,
// log-consts, and B fragment blobs (bf16 hi/lo) for mma.sync.
// ---------------------------------------------------------------------------
__global__ void setup_kernel(const float* __restrict__ phi,
                             const float* __restrict__ mu,
                             const float* __restrict__ sigma,
                             float* __restrict__ out, int Npts) {
    extern __shared__ float sm[];
    float (*A)[DD + 1] = (float (*)[DD + 1])sm;
    float (*M)[DD + 1] = (float (*)[DD + 1])(sm + DD * (DD + 1));
    float* red = sm + 2 * DD * (DD + 1);
    float* mus = red + DD;

    const int t = threadIdx.x;
    const int v = blockIdx.x / KK;
    const int k = blockIdx.x % KK;
    const float* S = sigma + (size_t)(v * KK + k) * DD * DD;

    for (int r = 0; r < DD; r++) A[r][t] = S[r * DD + t];
    __syncthreads();

    float dg = A[t][t] + 1e-6f;
    A[t][t] = dg;
    red[t] = 1.0f / (dg + 1e-12f);
    __syncthreads();
    for (int s = 64; s > 0; s >>= 1) {
        if (t < s) red[t] += red[t + s];
        __syncthreads();
    }
    if (t == 0) atomicAdd(&out[(size_t)4 * Npts + 1], red[0]);
    __syncthreads();

    for (int j = 0; j < DD; j++) {
        if (t == j) A[j][j] = sqrtf(A[j][j]);
        __syncthreads();
        float Ljj = A[j][j];
        float lij = 0.0f;
        if (t > j) {
            lij = A[t][j] / Ljj;
            A[t][j] = lij;
        }
        __syncthreads();
        if (t > j) {
            for (int l = j + 1; l <= t; l++)
                A[t][l] = fmaf(-lij, A[l][j], A[t][l]);
        }
        __syncthreads();
    }

    red[t] = logf(A[t][t]);
    __syncthreads();
    for (int s = 64; s > 0; s >>= 1) {
        if (t < s) red[t] += red[t + s];
        __syncthreads();
    }
    float logdet = fmaxf(2.0f * red[0], logf(1e-6f));
    __syncthreads();

    // M = L^{-1}; thread t owns column t
    for (int r = 0; r < DD; r++) M[r][t] = 0.0f;
    __syncthreads();
    const int c = t;
    for (int j = 0; j < DD; j++) {
        float s = 0.0f;
        for (int i = 0; i < j; i++) s = fmaf(A[j][i], M[i][c], s);
        if (j >= c) M[j][c] = (((j == c) ? 1.0f : 0.0f) - s) / A[j][j];
    }
    __syncthreads();

    mus[t] = mu[(size_t)(v * KK + k) * DD + t];
    __syncthreads();
    float u = 0.0f;
    for (int j = 0; j < DD; j++) u = fmaf(M[t][j], mus[j], u);
    g_u[(size_t)(v * KK + k) * DD + t] = u;

    // B fragments: element (col n, dim j) = M[n][j]; frag layout
    // [hl][kb][w][nt][lane][reg], u32 packs (k0, k0+1) bf16 pair.
    uint32_t* blob = g_Bfrag + (size_t)(v * KK + k) * 16384;
    for (int idx = t; idx < 16384; idx += DD) {
        int hl = idx >> 13;
        int rem = idx & 8191;
        int kb = rem >> 10;
        int rem2 = rem & 1023;
        int w = rem2 >> 7;
        int rem3 = rem2 & 127;
        int nt = rem3 >> 6;
        int rem4 = rem3 & 63;
        int lane = rem4 >> 1;
        int reg = rem4 & 1;
        int col = w * 16 + nt * 8 + (lane >> 2);
        int k0 = kb * 16 + (lane & 3) * 2 + reg * 8;
        unsigned short h0, l0, h1, l1;
        split_bf16(M[col][k0], h0, l0);
        split_bf16(M[col][k0 + 1], h1, l1);
        blob[idx] = hl ? ((uint32_t)l0 | ((uint32_t)l1 << 16))
                       : ((uint32_t)h0 | ((uint32_t)h1 << 16));
    }

    if (t == 0) {
        float pm = -3.0e38f;
        for (int i = 0; i < KK; i++) pm = fmaxf(pm, phi[v * KK + i]);
        float se = 0.0f;
        for (int i = 0; i < KK; i++) se += expf(phi[v * KK + i] - pm);
        float logpi = phi[v * KK + k] - pm - logf(se);
        g_logc[v * KK + k] = logpi - 0.5f * (float)DD * LOG2PI_F - 0.5f * logdet;
    }
}

// ---------------------------------------------------------------------------
// main: 128-pt tile per block; 8 warps each own a 16-col stripe per component.
// B stripe register-resident (reloaded per comp via LDG), A hi/lo staged in
// frag-packed smem (one LDS.128 per fragment). 3 bf16 passes -> f32 accum.
// smem: Ah 32K | Al 32K | slab 32K | us 4K | mah 4K = 104 KB
// ---------------------------------------------------------------------------
#define LOADB(comp_)                                                           \
    do {                                                                       \
        const uint32_t* bc_ = Bg + (comp_) * 16384 + w * 128 + lane * 2;       \
        _Pragma("unroll") for (int hl_ = 0; hl_ < 2; hl_++)                    \
        _Pragma("unroll") for (int kb_ = 0; kb_ < 8; kb_++)                    \
        _Pragma("unroll") for (int nt_ = 0; nt_ < 2; nt_++)                    \
            Bf[hl_][kb_][nt_] =                                                \
                *(const uint2*)(bc_ + hl_ * 8192 + kb_ * 1024 + nt_ * 64);     \
    } while (0)

__global__ void __launch_bounds__(256)
main_kernel(const float* __restrict__ z, float* __restrict__ out,
            int Npts, int bpv) {
    extern __shared__ __align__(16) unsigned char smraw[];
    uint32_t* Ah = (uint32_t*)smraw;                 // 32 KB
    uint32_t* Al = (uint32_t*)(smraw + 32768);       // 32 KB
    float* slab = (float*)(smraw + 65536);           // 32 KB [w][row][comp]
    float* us = (float*)(smraw + 98304);             // 4 KB
    float* mah = (float*)(smraw + 102400);           // 4 KB

    const int tid = threadIdx.x;
    const int w = tid >> 5;
    const int lane = tid & 31;
    const int tq = lane & 3;
    const int tr = lane >> 2;
    const int v = blockIdx.x / bpv;
    const int n0 = (blockIdx.x - v * bpv) * TN;

    const uint32_t* Bg = g_Bfrag + (size_t)v * KK * 16384;
    uint2 Bf[2][8][2];
    LOADB(0);  // issued early; latency hidden behind staging

    for (int i = tid; i < KK * DD; i += 256) us[i] = g_u[(size_t)v * KK * DD + i];

    // stage Z: split hi/lo bf16, fragment-packed layout
    const float* zr = z + (size_t)v * Npts * DD;
#pragma unroll
    for (int it = 0; it < 8; it++) {
        int idx = tid + it * 256;
        int p = idx >> 4;
        int oct = idx & 15;
        int n = n0 + p;
        float f[8];
        if (n < Npts) {
            const float4* src = (const float4*)(zr + (size_t)n * DD + oct * 8);
            float4 a = src[0], b = src[1];
            f[0] = a.x; f[1] = a.y; f[2] = a.z; f[3] = a.w;
            f[4] = b.x; f[5] = b.y; f[6] = b.z; f[7] = b.w;
        } else {
#pragma unroll
            for (int j = 0; j < 8; j++) f[j] = 0.0f;
        }
        int rb = p >> 4;
        int row_in = p & 15;
        int lane_row = row_in & 7;
        int rbit = row_in >> 3;
        int kb = oct >> 1;
        int khalf = oct & 1;
        int reg = (khalf << 1) | rbit;
        uint32_t base = (uint32_t)((rb * 8 + kb) * 128 + reg);
#pragma unroll
        for (int j = 0; j < 4; j++) {
            unsigned short h0, l0, h1, l1;
            split_bf16(f[2 * j], h0, l0);
            split_bf16(f[2 * j + 1], h1, l1);
            uint32_t off = base + (uint32_t)(lane_row * 4 + j) * 4;
            Ah[off] = (uint32_t)h0 | ((uint32_t)h1 << 16);
            Al[off] = (uint32_t)l0 | ((uint32_t)l1 << 16);
        }
    }
    __syncthreads();

    float acc[8][2][4];

    for (int comp = 0; comp < KK; comp++) {
#pragma unroll
        for (int rb = 0; rb < 8; rb++)
#pragma unroll
            for (int nt = 0; nt < 2; nt++)
#pragma unroll
                for (int r = 0; r < 4; r++) acc[rb][nt][r] = 0.0f;

#pragma unroll
        for (int kb = 0; kb < 8; kb++) {
#pragma unroll
            for (int rb = 0; rb < 8; rb++) {
                const uint32_t* ap = Ah + (rb * 8 + kb) * 128 + lane * 4;
                uint4 av = *(const uint4*)ap;
                uint4 lv = *(const uint4*)(ap + 8192);
                uint32_t a[4] = {av.x, av.y, av.z, av.w};
                uint32_t al[4] = {lv.x, lv.y, lv.z, lv.w};
                MMA16816(acc[rb][0], a, Bf[0][kb][0]);   // hh
                MMA16816(acc[rb][1], a, Bf[0][kb][1]);
                MMA16816(acc[rb][0], a, Bf[1][kb][0]);   // hl
                MMA16816(acc[rb][1], a, Bf[1][kb][1]);
                MMA16816(acc[rb][0], al, Bf[0][kb][0]);  // lh
                MMA16816(acc[rb][1], al, Bf[0][kb][1]);
            }
        }

        // prefetch next component's B (after last read of Bf this comp)
        if (comp + 1 < KK) LOADB(comp + 1);

        // epilogue: maha partials over this warp's 16 cols
        const float* uc = us + comp * DD + w * 16;
        float u0 = uc[tq * 2];
        float u1 = uc[tq * 2 + 1];
        float u2 = uc[8 + tq * 2];
        float u3 = uc[8 + tq * 2 + 1];
#pragma unroll
        for (int rb = 0; rb < 8; rb++) {
            float d00 = acc[rb][0][0] - u0;
            float d01 = acc[rb][0][1] - u1;
            float d10 = acc[rb][1][0] - u2;
            float d11 = acc[rb][1][1] - u3;
            float s0 = d00 * d00 + d01 * d01 + d10 * d10 + d11 * d11;
            float e00 = acc[rb][0][2] - u0;
            float e01 = acc[rb][0][3] - u1;
            float e10 = acc[rb][1][2] - u2;
            float e11 = acc[rb][1][3] - u3;
            float s1 = e00 * e00 + e01 * e01 + e10 * e10 + e11 * e11;
            s0 += __shfl_xor_sync(0xffffffffu, s0, 1);
            s0 += __shfl_xor_sync(0xffffffffu, s0, 2);
            s1 += __shfl_xor_sync(0xffffffffu, s1, 1);
            s1 += __shfl_xor_sync(0xffffffffu, s1, 2);
            if (tq == 0) {
                slab[w * 1024 + (rb * 16 + tr) * 8 + comp] = s0;
                slab[w * 1024 + (rb * 16 + tr + 8) * 8 + comp] = s1;
            }
        }
    }
    __syncthreads();

    // reduce warp slabs -> maha[row][comp]
    for (int i = tid; i < TN * KK; i += 256) {
        float s = 0.0f;
#pragma unroll
        for (int ww = 0; ww < 8; ww++) s += slab[ww * 1024 + i];
        mah[i] = s;
    }
    __syncthreads();

    if (tid < TN) {
        int n = n0 + tid;
        if (n < Npts) {
            float lp[KK];
            float m = -3.0e38f;
#pragma unroll
            for (int k = 0; k < KK; k++) {
                lp[k] = fmaf(-0.5f, mah[tid * KK + k], g_logc[v * KK + k]);
                m = fmaxf(m, lp[k]);
            }
            float se = 0.0f;
#pragma unroll
            for (int k = 0; k < KK; k++) se += expf(lp[k] - m);
            out[(size_t)n * VV + v] = -(m + logf(se));
        }
    }
}

// ---------------------------------------------------------------------------
__global__ void finalize_kernel(float* __restrict__ out, int Npts) {
    int n = blockIdx.x * blockDim.x + threadIdx.x;
    float esum = 0.0f;
    if (n < Npts) {
        float e0 = out[2 * n];
        float e1 = out[2 * n + 1];
        float m = fminf(e0, e1);
        float a = expf(m - e0);
        float b = expf(m - e1);
        float inv = 1.0f / (a + b);
        size_t wb = (size_t)2 * Npts;
        out[wb + 2 * n] = a * inv;
        out[wb + 2 * n + 1] = b * inv;
        esum = e0 + e1;
    }
    __shared__ float wsum[8];
    for (int o = 16; o; o >>= 1) esum += __shfl_xor_sync(0xffffffffu, esum, o);
    if ((threadIdx.x & 31) == 0) wsum[threadIdx.x >> 5] = esum;
    __syncthreads();
    if (threadIdx.x < 8) {
        float x = wsum[threadIdx.x];
        for (int o = 4; o; o >>= 1) x += __shfl_xor_sync(0x000000ffu, x, o);
        if (threadIdx.x == 0) atomicAdd(&out[(size_t)4 * Npts], x);
    }
}

// ---------------------------------------------------------------------------
extern "C" void kernel_launch(void* const* d_in, const int* in_sizes, int n_in,
                              void* d_out, int out_size) {
    (void)n_in;
    (void)out_size;
    const float* z = (const float*)d_in[0];
    const float* phi = (const float*)d_in[1];
    const float* mu = (const float*)d_in[2];
    const float* sigma = (const float*)d_in[3];
    float* out = (float*)d_out;

    const int Npts = in_sizes[0] / (VV * DD);

    const int SETUP_SMEM = (2 * DD * (DD + 1) + 2 * DD) * (int)sizeof(float);
    const int MAIN_SMEM = 106496;  // 104 KB

    cudaFuncSetAttribute(setup_kernel,
                         cudaFuncAttributeMaxDynamicSharedMemorySize, SETUP_SMEM);
    cudaFuncSetAttribute(main_kernel,
                         cudaFuncAttributeMaxDynamicSharedMemorySize, MAIN_SMEM);

    init_kernel<<<1, 1>>>(out, Npts);
    setup_kernel<<<VV * KK, DD, SETUP_SMEM>>>(phi, mu, sigma, out, Npts);

    const int bpv = (Npts + TN - 1) / TN;
    main_kernel<<<VV * bpv, 256, MAIN_SMEM>>>(z, out, Npts, bpv);

    finalize_kernel<<<(Npts + 255) / 256, 256>>>(out, Npts);
}

// round 4
// speedup vs baseline: 2.1933x; 1.0059x over previous
#include <cuda_runtime.h>
#include <cuda_bf16.h>
#include <math.h>
#include <stdint.h>

#define VV 2
#define KK 8
#define DD 128
#define TN 128
#define LOG2PI_F 1.8378770664093453f

// B fragments (triangular-packed): per (v,comp): [w][slot0..8][hl][lane][reg]
// 9216 u32 per comp -> 576 KB total (L2-resident).
__device__ uint32_t g_Bfrag[VV * KK * 9216];
__device__ float g_u[VV * KK * DD];
__device__ float g_logc[VV * KK];

__device__ __forceinline__ void split_bf16(float x, unsigned short& h, unsigned short& l) {
    __nv_bfloat16 hb = __float2bfloat16(x);
    float r = x - __bfloat162float(hb);
    __nv_bfloat16 lb = __float2bfloat16(r);
    h = __bfloat16_as_ushort(hb);
    l = __bfloat16_as_ushort(lb);
}

#define MMA16816(c, a, b)                                                      \
    asm volatile(                                                              \
        "mma.sync.aligned.m16n8k16.row.col.f32.bf16.bf16.f32 "                 \
        "{%0,%1,%2,%3}, {%4,%5,%6,%7}, {%8,%9}, {%0,%1,%2,%3};"                \
        : "+f"((c)[0]), "+f"((c)[1]), "+f"((c)[2]), "+f"((c)[3])               \
        : "r"((a)[0]), "r"((a)[1]), "r"((a)[2]), "r"((a)[3]),                  \
          "r"((b).x), "r"((b).y))

// ---------------------------------------------------------------------------
__global__ void init_kernel(float* __restrict__ out, int Npts) {
    size_t base = (size_t)4 * Npts;
    out[base] = 0.0f;
    out[base + 1] = 0.0f;
}

// ---------------------------------------------------------------------------
// setup: per (v,k) Cholesky of sigma+1e-6 I, M=L^-1, u=M*mu, penalty,
// log-consts, triangular-packed B fragment blobs.
// ---------------------------------------------------------------------------
__global__ void setup_kernel(const float* __restrict__ phi,
                             const float* __restrict__ mu,
                             const float* __restrict__ sigma,
                             float* __restrict__ out, int Npts) {
    extern __shared__ float sm[];
    float (*A)[DD + 1] = (float (*)[DD + 1])sm;
    float (*M)[DD + 1] = (float (*)[DD + 1])(sm + DD * (DD + 1));
    float* red = sm + 2 * DD * (DD + 1);
    float* mus = red + DD;

    const int t = threadIdx.x;
    const int v = blockIdx.x / KK;
    const int k = blockIdx.x % KK;
    const float* S = sigma + (size_t)(v * KK + k) * DD * DD;

    for (int r = 0; r < DD; r++) A[r][t] = S[r * DD + t];
    __syncthreads();

    float dg = A[t][t] + 1e-6f;
    A[t][t] = dg;
    red[t] = 1.0f / (dg + 1e-12f);
    __syncthreads();
    for (int s = 64; s > 0; s >>= 1) {
        if (t < s) red[t] += red[t + s];
        __syncthreads();
    }
    if (t == 0) atomicAdd(&out[(size_t)4 * Npts + 1], red[0]);
    __syncthreads();

    for (int j = 0; j < DD; j++) {
        if (t == j) A[j][j] = sqrtf(A[j][j]);
        __syncthreads();
        float Ljj = A[j][j];
        float lij = 0.0f;
        if (t > j) {
            lij = A[t][j] / Ljj;
            A[t][j] = lij;
        }
        __syncthreads();
        if (t > j) {
#pragma unroll 4
            for (int l = j + 1; l <= t; l++)
                A[t][l] = fmaf(-lij, A[l][j], A[t][l]);
        }
        __syncthreads();
    }

    red[t] = logf(A[t][t]);
    __syncthreads();
    for (int s = 64; s > 0; s >>= 1) {
        if (t < s) red[t] += red[t + s];
        __syncthreads();
    }
    float logdet = fmaxf(2.0f * red[0], logf(1e-6f));
    __syncthreads();

    // M = L^{-1}; thread t owns column t; 4-way partial sums
    for (int r = 0; r < DD; r++) M[r][t] = 0.0f;
    __syncthreads();
    const int c = t;
    for (int j = 0; j < DD; j++) {
        float s0 = 0.0f, s1 = 0.0f, s2 = 0.0f, s3 = 0.0f;
        int jr = j & ~3;
        for (int i = 0; i < jr; i += 4) {
            s0 = fmaf(A[j][i], M[i][c], s0);
            s1 = fmaf(A[j][i + 1], M[i + 1][c], s1);
            s2 = fmaf(A[j][i + 2], M[i + 2][c], s2);
            s3 = fmaf(A[j][i + 3], M[i + 3][c], s3);
        }
        for (int i = jr; i < j; i++) s0 = fmaf(A[j][i], M[i][c], s0);
        float s = (s0 + s1) + (s2 + s3);
        if (j >= c) M[j][c] = (((j == c) ? 1.0f : 0.0f) - s) / A[j][j];
    }
    __syncthreads();

    mus[t] = mu[(size_t)(v * KK + k) * DD + t];
    __syncthreads();
    float u = 0.0f;
    for (int j = 0; j < DD; j++) u = fmaf(M[t][j], mus[j], u);
    g_u[(size_t)(v * KK + k) * DD + t] = u;

    // triangular-packed B frags: warp w covers col-blocks bA=w, bB=15-w.
    // slot s<nA -> (bA, kb=s); else (bB, kb=s-nA); nA = w/2+1; 9 slots always.
    uint32_t* blob = g_Bfrag + (size_t)(v * KK + k) * 9216;
    for (int idx = t; idx < 9216; idx += DD) {
        int reg = idx & 1;
        int lane = (idx >> 1) & 31;
        int hl = (idx >> 6) & 1;
        int ws = idx >> 7;            // w*9+s
        int w = ws / 9;
        int s = ws - w * 9;
        int nA = (w >> 1) + 1;
        int b = (s < nA) ? w : 15 - w;
        int kb = (s < nA) ? s : s - nA;
        int col = b * 8 + (lane >> 2);
        int k0 = kb * 16 + (lane & 3) * 2 + reg * 8;
        unsigned short h0, l0, h1, l1;
        split_bf16(M[col][k0], h0, l0);
        split_bf16(M[col][k0 + 1], h1, l1);
        blob[idx] = hl ? ((uint32_t)l0 | ((uint32_t)l1 << 16))
                       : ((uint32_t)h0 | ((uint32_t)h1 << 16));
    }

    if (t == 0) {
        float pm = -3.0e38f;
        for (int i = 0; i < KK; i++) pm = fmaxf(pm, phi[v * KK + i]);
        float se = 0.0f;
        for (int i = 0; i < KK; i++) se += expf(phi[v * KK + i] - pm);
        float logpi = phi[v * KK + k] - pm - logf(se);
        g_logc[v * KK + k] = logpi - 0.5f * (float)DD * LOG2PI_F - 0.5f * logdet;
    }
}

// ---------------------------------------------------------------------------
// main: one block per 128-pt tile, BOTH views processed in-block (weights +
// totals fused). Per comp: triangular MMA (skip zero blocks), balanced warp
// pairing (bA=w, bB=15-w). 3 bf16 passes. smem: Ah 32K|Al 32K|slab 32K|us 4K|
// mah 4K = 104 KB.
// ---------------------------------------------------------------------------
#define LOADB(comp_)                                                           \
    do {                                                                       \
        const uint32_t* bc_ = Bg + (size_t)(comp_)*9216 + w * 9 * 128 + lane * 2; \
        _Pragma("unroll") for (int s_ = 0; s_ < 4; s_++) if (s_ < nA)          \
            _Pragma("unroll") for (int hl_ = 0; hl_ < 2; hl_++)                \
                BfA[s_][hl_] = *(const uint2*)(bc_ + (s_ * 2 + hl_) * 64);     \
        _Pragma("unroll") for (int s_ = 0; s_ < 8; s_++) if (s_ < nB)          \
            _Pragma("unroll") for (int hl_ = 0; hl_ < 2; hl_++)                \
                BfB[s_][hl_] = *(const uint2*)(bc_ + ((nA + s_) * 2 + hl_) * 64); \
    } while (0)

__global__ void __launch_bounds__(256)
main_kernel(const float* __restrict__ z, float* __restrict__ out, int Npts) {
    extern __shared__ __align__(16) unsigned char smraw[];
    uint32_t* Ah = (uint32_t*)smraw;                 // 32 KB
    uint32_t* Al = (uint32_t*)(smraw + 32768);       // 32 KB
    float* slab = (float*)(smraw + 65536);           // 32 KB [w][row][comp]
    float* us = (float*)(smraw + 98304);             // 4 KB
    float* mah = (float*)(smraw + 102400);           // 4 KB

    const int tid = threadIdx.x;
    const int w = tid >> 5;
    const int lane = tid & 31;
    const int tq = lane & 3;
    const int tr = lane >> 2;
    const int n0 = blockIdx.x * TN;
    const int nA = (w >> 1) + 1;
    const int nB = 9 - nA;

    uint2 BfA[4][2], BfB[8][2];
    float e_prev = 0.0f;      // view-0 energy for this thread's point
    float esum = 0.0f;

    for (int v = 0; v < VV; v++) {
        const uint32_t* Bg = g_Bfrag + (size_t)v * KK * 9216;
        LOADB(0);

        for (int i = tid; i < KK * DD; i += 256)
            us[i] = g_u[(size_t)v * KK * DD + i];

        // stage Z tile: split hi/lo bf16, fragment-packed
        const float* zr = z + (size_t)v * Npts * DD;
#pragma unroll
        for (int it = 0; it < 8; it++) {
            int idx = tid + it * 256;
            int p = idx >> 4;
            int oct = idx & 15;
            int n = n0 + p;
            float f[8];
            if (n < Npts) {
                const float4* src = (const float4*)(zr + (size_t)n * DD + oct * 8);
                float4 a = src[0], b = src[1];
                f[0] = a.x; f[1] = a.y; f[2] = a.z; f[3] = a.w;
                f[4] = b.x; f[5] = b.y; f[6] = b.z; f[7] = b.w;
            } else {
#pragma unroll
                for (int j = 0; j < 8; j++) f[j] = 0.0f;
            }
            int rb = p >> 4;
            int row_in = p & 15;
            int lane_row = row_in & 7;
            int rbit = row_in >> 3;
            int kb = oct >> 1;
            int khalf = oct & 1;
            int reg = (khalf << 1) | rbit;
            uint32_t base = (uint32_t)((rb * 8 + kb) * 128 + reg);
#pragma unroll
            for (int j = 0; j < 4; j++) {
                unsigned short h0, l0, h1, l1;
                split_bf16(f[2 * j], h0, l0);
                split_bf16(f[2 * j + 1], h1, l1);
                uint32_t off = base + (uint32_t)(lane_row * 4 + j) * 4;
                Ah[off] = (uint32_t)h0 | ((uint32_t)h1 << 16);
                Al[off] = (uint32_t)l0 | ((uint32_t)l1 << 16);
            }
        }
        __syncthreads();

        float accA[8][4], accB[8][4];

        for (int comp = 0; comp < KK; comp++) {
#pragma unroll
            for (int rb = 0; rb < 8; rb++)
#pragma unroll
                for (int r = 0; r < 4; r++) {
                    accA[rb][r] = 0.0f;
                    accB[rb][r] = 0.0f;
                }

            // col-block bA = w: kb < nA
#pragma unroll
            for (int kb = 0; kb < 4; kb++)
                if (kb < nA) {
#pragma unroll
                    for (int rb = 0; rb < 8; rb++) {
                        const uint32_t* ap = Ah + (rb * 8 + kb) * 128 + lane * 4;
                        uint4 av = *(const uint4*)ap;
                        uint4 lv = *(const uint4*)(ap + 8192);
                        uint32_t a[4] = {av.x, av.y, av.z, av.w};
                        uint32_t al[4] = {lv.x, lv.y, lv.z, lv.w};
                        MMA16816(accA[rb], a, BfA[kb][0]);
                        MMA16816(accA[rb], a, BfA[kb][1]);
                        MMA16816(accA[rb], al, BfA[kb][0]);
                    }
                }
            // col-block bB = 15-w: kb < nB
#pragma unroll
            for (int kb = 0; kb < 8; kb++)
                if (kb < nB) {
#pragma unroll
                    for (int rb = 0; rb < 8; rb++) {
                        const uint32_t* ap = Ah + (rb * 8 + kb) * 128 + lane * 4;
                        uint4 av = *(const uint4*)ap;
                        uint4 lv = *(const uint4*)(ap + 8192);
                        uint32_t a[4] = {av.x, av.y, av.z, av.w};
                        uint32_t al[4] = {lv.x, lv.y, lv.z, lv.w};
                        MMA16816(accB[rb], a, BfB[kb][0]);
                        MMA16816(accB[rb], a, BfB[kb][1]);
                        MMA16816(accB[rb], al, BfB[kb][0]);
                    }
                }

            if (comp + 1 < KK) LOADB(comp + 1);

            // epilogue: maha partials over this warp's 16 cols (bA + bB)
            const float* uc = us + comp * DD;
            float uA0 = uc[w * 8 + tq * 2];
            float uA1 = uc[w * 8 + tq * 2 + 1];
            float uB0 = uc[(15 - w) * 8 + tq * 2];
            float uB1 = uc[(15 - w) * 8 + tq * 2 + 1];
#pragma unroll
            for (int rb = 0; rb < 8; rb++) {
                float d0 = accA[rb][0] - uA0;
                float d1 = accA[rb][1] - uA1;
                float d2 = accB[rb][0] - uB0;
                float d3 = accB[rb][1] - uB1;
                float s0 = d0 * d0 + d1 * d1 + d2 * d2 + d3 * d3;
                float e0 = accA[rb][2] - uA0;
                float e1 = accA[rb][3] - uA1;
                float e2 = accB[rb][2] - uB0;
                float e3 = accB[rb][3] - uB1;
                float s1 = e0 * e0 + e1 * e1 + e2 * e2 + e3 * e3;
                s0 += __shfl_xor_sync(0xffffffffu, s0, 1);
                s0 += __shfl_xor_sync(0xffffffffu, s0, 2);
                s1 += __shfl_xor_sync(0xffffffffu, s1, 1);
                s1 += __shfl_xor_sync(0xffffffffu, s1, 2);
                if (tq == 0) {
                    slab[w * 1024 + (rb * 16 + tr) * 8 + comp] = s0;
                    slab[w * 1024 + (rb * 16 + tr + 8) * 8 + comp] = s1;
                }
            }
        }
        __syncthreads();

        // reduce warp slabs -> maha[row][comp]
        for (int i = tid; i < TN * KK; i += 256) {
            float s = 0.0f;
#pragma unroll
            for (int ww = 0; ww < 8; ww++) s += slab[ww * 1024 + i];
            mah[i] = s;
        }
        __syncthreads();

        if (tid < TN) {
            int n = n0 + tid;
            if (n < Npts) {
                float lp[KK];
                float m = -3.0e38f;
#pragma unroll
                for (int k = 0; k < KK; k++) {
                    lp[k] = fmaf(-0.5f, mah[tid * KK + k], g_logc[v * KK + k]);
                    m = fmaxf(m, lp[k]);
                }
                float se = 0.0f;
#pragma unroll
                for (int k = 0; k < KK; k++) se += expf(lp[k] - m);
                float e = -(m + logf(se));
                out[(size_t)n * VV + v] = e;
                if (v == 0) {
                    e_prev = e;
                } else {
                    float mm = fminf(e_prev, e);
                    float a = expf(mm - e_prev);
                    float b = expf(mm - e);
                    float inv = 1.0f / (a + b);
                    size_t wb = (size_t)2 * Npts;
                    out[wb + (size_t)n * VV] = a * inv;
                    out[wb + (size_t)n * VV + 1] = b * inv;
                    esum = e_prev + e;
                }
            }
        }
        __syncthreads();   // before smem reuse by next view
    }

    // block-reduce esum -> total_energies
    __shared__ float wsum[8];
    for (int o = 16; o; o >>= 1) esum += __shfl_xor_sync(0xffffffffu, esum, o);
    if (lane == 0) wsum[w] = esum;
    __syncthreads();
    if (tid < 8) {
        float x = wsum[tid];
        for (int o = 4; o; o >>= 1) x += __shfl_xor_sync(0x000000ffu, x, o);
        if (tid == 0) atomicAdd(&out[(size_t)4 * Npts], x);
    }
}

// ---------------------------------------------------------------------------
extern "C" void kernel_launch(void* const* d_in, const int* in_sizes, int n_in,
                              void* d_out, int out_size) {
    (void)n_in;
    (void)out_size;
    const float* z = (const float*)d_in[0];
    const float* phi = (const float*)d_in[1];
    const float* mu = (const float*)d_in[2];
    const float* sigma = (const float*)d_in[3];
    float* out = (float*)d_out;

    const int Npts = in_sizes[0] / (VV * DD);

    const int SETUP_SMEM = (2 * DD * (DD + 1) + 2 * DD) * (int)sizeof(float);
    const int MAIN_SMEM = 106496;  // 104 KB

    cudaFuncSetAttribute(setup_kernel,
                         cudaFuncAttributeMaxDynamicSharedMemorySize, SETUP_SMEM);
    cudaFuncSetAttribute(main_kernel,
                         cudaFuncAttributeMaxDynamicSharedMemorySize, MAIN_SMEM);

    init_kernel<<<1, 1>>>(out, Npts);
    setup_kernel<<<VV * KK, DD, SETUP_SMEM>>>(phi, mu, sigma, out, Npts);

    const int bpv = (Npts + TN - 1) / TN;
    main_kernel<<<bpv, 256, MAIN_SMEM>>>(z, out, Npts);
}

// round 5
// speedup vs baseline: 2.4544x; 1.1191x over previous
#include <cuda_runtime.h>
#include <cuda_bf16.h>
#include <math.h>
#include <stdint.h>

#define VV 2
#define KK 8
#define DD 128
#define TN 128
#define LOG2PI_F 1.8378770664093453f

// B fragments (triangular-packed): per (v,comp): [w][slot0..8][hl][lane][reg]
// slot s<nA -> (b=w, kb=s); s>=nA -> (b=15-w, kb=s-nA); nA = w/2+1.
__device__ uint32_t g_Bfrag[VV * KK * 9216];
__device__ float g_u[VV * KK * DD];
__device__ float g_logc[VV * KK];

__device__ __forceinline__ void split_bf16(float x, unsigned short& h, unsigned short& l) {
    __nv_bfloat16 hb = __float2bfloat16(x);
    float r = x - __bfloat162float(hb);
    __nv_bfloat16 lb = __float2bfloat16(r);
    h = __bfloat16_as_ushort(hb);
    l = __bfloat16_as_ushort(lb);
}

#define MMA16816(c, a, b)                                                      \
    asm volatile(                                                              \
        "mma.sync.aligned.m16n8k16.row.col.f32.bf16.bf16.f32 "                 \
        "{%0,%1,%2,%3}, {%4,%5,%6,%7}, {%8,%9}, {%0,%1,%2,%3};"                \
        : "+f"((c)[0]), "+f"((c)[1]), "+f"((c)[2]), "+f"((c)[3])               \
        : "r"((a)[0]), "r"((a)[1]), "r"((a)[2]), "r"((a)[3]),                  \
          "r"((b).x), "r"((b).y))

// ---------------------------------------------------------------------------
__global__ void init_kernel(float* __restrict__ out, int Npts) {
    size_t base = (size_t)4 * Npts;
    out[base] = 0.0f;
    out[base + 1] = 0.0f;
}

// ---------------------------------------------------------------------------
// setup: per (v,k) Cholesky of sigma+1e-6 I, M=L^-1, u=M*mu, penalty,
// log-consts, triangular-packed B fragment blobs. (unchanged from R4)
// ---------------------------------------------------------------------------
__global__ void setup_kernel(const float* __restrict__ phi,
                             const float* __restrict__ mu,
                             const float* __restrict__ sigma,
                             float* __restrict__ out, int Npts) {
    extern __shared__ float sm[];
    float (*A)[DD + 1] = (float (*)[DD + 1])sm;
    float (*M)[DD + 1] = (float (*)[DD + 1])(sm + DD * (DD + 1));
    float* red = sm + 2 * DD * (DD + 1);
    float* mus = red + DD;

    const int t = threadIdx.x;
    const int v = blockIdx.x / KK;
    const int k = blockIdx.x % KK;
    const float* S = sigma + (size_t)(v * KK + k) * DD * DD;

    for (int r = 0; r < DD; r++) A[r][t] = S[r * DD + t];
    __syncthreads();

    float dg = A[t][t] + 1e-6f;
    A[t][t] = dg;
    red[t] = 1.0f / (dg + 1e-12f);
    __syncthreads();
    for (int s = 64; s > 0; s >>= 1) {
        if (t < s) red[t] += red[t + s];
        __syncthreads();
    }
    if (t == 0) atomicAdd(&out[(size_t)4 * Npts + 1], red[0]);
    __syncthreads();

    for (int j = 0; j < DD; j++) {
        if (t == j) A[j][j] = sqrtf(A[j][j]);
        __syncthreads();
        float Ljj = A[j][j];
        float lij = 0.0f;
        if (t > j) {
            lij = A[t][j] / Ljj;
            A[t][j] = lij;
        }
        __syncthreads();
        if (t > j) {
#pragma unroll 4
            for (int l = j + 1; l <= t; l++)
                A[t][l] = fmaf(-lij, A[l][j], A[t][l]);
        }
        __syncthreads();
    }

    red[t] = logf(A[t][t]);
    __syncthreads();
    for (int s = 64; s > 0; s >>= 1) {
        if (t < s) red[t] += red[t + s];
        __syncthreads();
    }
    float logdet = fmaxf(2.0f * red[0], logf(1e-6f));
    __syncthreads();

    for (int r = 0; r < DD; r++) M[r][t] = 0.0f;
    __syncthreads();
    const int c = t;
    for (int j = 0; j < DD; j++) {
        float s0 = 0.0f, s1 = 0.0f, s2 = 0.0f, s3 = 0.0f;
        int jr = j & ~3;
        for (int i = 0; i < jr; i += 4) {
            s0 = fmaf(A[j][i], M[i][c], s0);
            s1 = fmaf(A[j][i + 1], M[i + 1][c], s1);
            s2 = fmaf(A[j][i + 2], M[i + 2][c], s2);
            s3 = fmaf(A[j][i + 3], M[i + 3][c], s3);
        }
        for (int i = jr; i < j; i++) s0 = fmaf(A[j][i], M[i][c], s0);
        float s = (s0 + s1) + (s2 + s3);
        if (j >= c) M[j][c] = (((j == c) ? 1.0f : 0.0f) - s) / A[j][j];
    }
    __syncthreads();

    mus[t] = mu[(size_t)(v * KK + k) * DD + t];
    __syncthreads();
    float u = 0.0f;
    for (int j = 0; j < DD; j++) u = fmaf(M[t][j], mus[j], u);
    g_u[(size_t)(v * KK + k) * DD + t] = u;

    uint32_t* blob = g_Bfrag + (size_t)(v * KK + k) * 9216;
    for (int idx = t; idx < 9216; idx += DD) {
        int reg = idx & 1;
        int lane = (idx >> 1) & 31;
        int hl = (idx >> 6) & 1;
        int ws = idx >> 7;
        int w = ws / 9;
        int s = ws - w * 9;
        int nA = (w >> 1) + 1;
        int b = (s < nA) ? w : 15 - w;
        int kb = (s < nA) ? s : s - nA;
        int col = b * 8 + (lane >> 2);
        int k0 = kb * 16 + (lane & 3) * 2 + reg * 8;
        unsigned short h0, l0, h1, l1;
        split_bf16(M[col][k0], h0, l0);
        split_bf16(M[col][k0 + 1], h1, l1);
        blob[idx] = hl ? ((uint32_t)l0 | ((uint32_t)l1 << 16))
                       : ((uint32_t)h0 | ((uint32_t)h1 << 16));
    }

    if (t == 0) {
        float pm = -3.0e38f;
        for (int i = 0; i < KK; i++) pm = fmaxf(pm, phi[v * KK + i]);
        float se = 0.0f;
        for (int i = 0; i < KK; i++) se += expf(phi[v * KK + i] - pm);
        float logpi = phi[v * KK + k] - pm - logf(se);
        g_logc[v * KK + k] = logpi - 0.5f * (float)DD * LOG2PI_F - 0.5f * logdet;
    }
}

// ---------------------------------------------------------------------------
// templated per-view mainloop: NA compile-time, all loops constant-bound.
// No __syncthreads inside (slab region is warp-private).
// ---------------------------------------------------------------------------
template <int NA>
__device__ __forceinline__ void view_mainloop(
    const uint32_t* __restrict__ Bg, const uint32_t* __restrict__ Ah,
    float* __restrict__ slab, const float* __restrict__ us,
    int w, int lane) {
    constexpr int NB = 9 - NA;
    const int tq = lane & 3;
    const int tr = lane >> 2;

    uint2 BfA[NA][2], BfB[NB][2];
    {
        const uint32_t* bc = Bg + w * 9 * 128 + lane * 2;
#pragma unroll
        for (int s = 0; s < NA; s++) {
            BfA[s][0] = *(const uint2*)(bc + (s * 2 + 0) * 64);
            BfA[s][1] = *(const uint2*)(bc + (s * 2 + 1) * 64);
        }
#pragma unroll
        for (int s = 0; s < NB; s++) {
            BfB[s][0] = *(const uint2*)(bc + ((NA + s) * 2 + 0) * 64);
            BfB[s][1] = *(const uint2*)(bc + ((NA + s) * 2 + 1) * 64);
        }
    }

    for (int comp = 0; comp < KK; comp++) {
        float accA[8][4], accB[8][4];
#pragma unroll
        for (int rb = 0; rb < 8; rb++)
#pragma unroll
            for (int r = 0; r < 4; r++) {
                accA[rb][r] = 0.0f;
                accB[rb][r] = 0.0f;
            }

#pragma unroll
        for (int kb = 0; kb < NB; kb++) {
#pragma unroll
            for (int rb = 0; rb < 8; rb++) {
                const uint32_t* ap = Ah + (rb * 8 + kb) * 128 + lane * 4;
                uint4 av = *(const uint4*)ap;
                uint4 lv = *(const uint4*)(ap + 8192);
                uint32_t a[4] = {av.x, av.y, av.z, av.w};
                uint32_t al[4] = {lv.x, lv.y, lv.z, lv.w};
                MMA16816(accB[rb], a, BfB[kb][0]);
                if (kb < NA) MMA16816(accA[rb], a, BfA[kb][0]);
                MMA16816(accB[rb], a, BfB[kb][1]);
                if (kb < NA) MMA16816(accA[rb], a, BfA[kb][1]);
                MMA16816(accB[rb], al, BfB[kb][0]);
                if (kb < NA) MMA16816(accA[rb], al, BfA[kb][0]);
            }
        }

        // prefetch next comp's B fragments
        if (comp + 1 < KK) {
            const uint32_t* bc = Bg + (size_t)(comp + 1) * 9216 + w * 9 * 128 + lane * 2;
#pragma unroll
            for (int s = 0; s < NA; s++) {
                BfA[s][0] = *(const uint2*)(bc + (s * 2 + 0) * 64);
                BfA[s][1] = *(const uint2*)(bc + (s * 2 + 1) * 64);
            }
#pragma unroll
            for (int s = 0; s < NB; s++) {
                BfB[s][0] = *(const uint2*)(bc + ((NA + s) * 2 + 0) * 64);
                BfB[s][1] = *(const uint2*)(bc + ((NA + s) * 2 + 1) * 64);
            }
        }

        // epilogue: maha partials over this warp's 16 cols (bA=w, bB=15-w)
        const float* uc = us + comp * DD;
        float uA0 = uc[w * 8 + tq * 2];
        float uA1 = uc[w * 8 + tq * 2 + 1];
        float uB0 = uc[(15 - w) * 8 + tq * 2];
        float uB1 = uc[(15 - w) * 8 + tq * 2 + 1];
#pragma unroll
        for (int rb = 0; rb < 8; rb++) {
            float d0 = accA[rb][0] - uA0;
            float d1 = accA[rb][1] - uA1;
            float d2 = accB[rb][0] - uB0;
            float d3 = accB[rb][1] - uB1;
            float s0 = d0 * d0 + d1 * d1 + d2 * d2 + d3 * d3;
            float e0 = accA[rb][2] - uA0;
            float e1 = accA[rb][3] - uA1;
            float e2 = accB[rb][2] - uB0;
            float e3 = accB[rb][3] - uB1;
            float s1 = e0 * e0 + e1 * e1 + e2 * e2 + e3 * e3;
            s0 += __shfl_xor_sync(0xffffffffu, s0, 1);
            s0 += __shfl_xor_sync(0xffffffffu, s0, 2);
            s1 += __shfl_xor_sync(0xffffffffu, s1, 1);
            s1 += __shfl_xor_sync(0xffffffffu, s1, 2);
            if (tq == 0) {
                slab[w * 1024 + (rb * 16 + tr) * 8 + comp] = s0;
                slab[w * 1024 + (rb * 16 + tr + 8) * 8 + comp] = s1;
            }
        }
    }
}

// ---------------------------------------------------------------------------
// main: one block per 128-pt tile, both views, fused weights + totals.
// smem: Ah 32K | Al 32K | slab 32K | us 4K | mah 4K = 104 KB
// ---------------------------------------------------------------------------
__global__ void __launch_bounds__(256)
main_kernel(const float* __restrict__ z, float* __restrict__ out, int Npts) {
    extern __shared__ __align__(16) unsigned char smraw[];
    uint32_t* Ah = (uint32_t*)smraw;                 // 32 KB (+ Al at +8192 u32)
    float* slab = (float*)(smraw + 65536);           // 32 KB [w][row][comp]
    float* us = (float*)(smraw + 98304);             // 4 KB
    float* mah = (float*)(smraw + 102400);           // 4 KB

    const int tid = threadIdx.x;
    const int w = tid >> 5;
    const int lane = tid & 31;
    const int n0 = blockIdx.x * TN;

    float e_prev = 0.0f;
    float esum = 0.0f;

    for (int v = 0; v < VV; v++) {
        const uint32_t* Bg = g_Bfrag + (size_t)v * KK * 9216;

        for (int i = tid; i < KK * DD; i += 256)
            us[i] = g_u[(size_t)v * KK * DD + i];

        // stage Z tile: split hi/lo bf16, fragment-packed
        const float* zr = z + (size_t)v * Npts * DD;
#pragma unroll
        for (int it = 0; it < 8; it++) {
            int idx = tid + it * 256;
            int p = idx >> 4;
            int oct = idx & 15;
            int n = n0 + p;
            float f[8];
            if (n < Npts) {
                const float4* src = (const float4*)(zr + (size_t)n * DD + oct * 8);
                float4 a = src[0], b = src[1];
                f[0] = a.x; f[1] = a.y; f[2] = a.z; f[3] = a.w;
                f[4] = b.x; f[5] = b.y; f[6] = b.z; f[7] = b.w;
            } else {
#pragma unroll
                for (int j = 0; j < 8; j++) f[j] = 0.0f;
            }
            int rb = p >> 4;
            int row_in = p & 15;
            int lane_row = row_in & 7;
            int rbit = row_in >> 3;
            int kb = oct >> 1;
            int khalf = oct & 1;
            int reg = (khalf << 1) | rbit;
            uint32_t base = (uint32_t)((rb * 8 + kb) * 128 + reg);
#pragma unroll
            for (int j = 0; j < 4; j++) {
                unsigned short h0, l0, h1, l1;
                split_bf16(f[2 * j], h0, l0);
                split_bf16(f[2 * j + 1], h1, l1);
                uint32_t off = base + (uint32_t)(lane_row * 4 + j) * 4;
                Ah[off] = (uint32_t)h0 | ((uint32_t)h1 << 16);
                Ah[off + 8192] = (uint32_t)l0 | ((uint32_t)l1 << 16);
            }
        }
        __syncthreads();

        switch (w >> 1) {
            case 0: view_mainloop<1>(Bg, Ah, slab, us, w, lane); break;
            case 1: view_mainloop<2>(Bg, Ah, slab, us, w, lane); break;
            case 2: view_mainloop<3>(Bg, Ah, slab, us, w, lane); break;
            default: view_mainloop<4>(Bg, Ah, slab, us, w, lane); break;
        }
        __syncthreads();

        // reduce warp slabs -> maha[row][comp]
        for (int i = tid; i < TN * KK; i += 256) {
            float s = 0.0f;
#pragma unroll
            for (int ww = 0; ww < 8; ww++) s += slab[ww * 1024 + i];
            mah[i] = s;
        }
        __syncthreads();

        if (tid < TN) {
            int n = n0 + tid;
            if (n < Npts) {
                float lp[KK];
                float m = -3.0e38f;
#pragma unroll
                for (int k = 0; k < KK; k++) {
                    lp[k] = fmaf(-0.5f, mah[tid * KK + k], g_logc[v * KK + k]);
                    m = fmaxf(m, lp[k]);
                }
                float se = 0.0f;
#pragma unroll
                for (int k = 0; k < KK; k++) se += expf(lp[k] - m);
                float e = -(m + logf(se));
                out[(size_t)n * VV + v] = e;
                if (v == 0) {
                    e_prev = e;
                } else {
                    float mm = fminf(e_prev, e);
                    float a = expf(mm - e_prev);
                    float b = expf(mm - e);
                    float inv = 1.0f / (a + b);
                    size_t wb = (size_t)2 * Npts;
                    out[wb + (size_t)n * VV] = a * inv;
                    out[wb + (size_t)n * VV + 1] = b * inv;
                    esum = e_prev + e;
                }
            }
        }
        __syncthreads();
    }

    __shared__ float wsum[8];
    for (int o = 16; o; o >>= 1) esum += __shfl_xor_sync(0xffffffffu, esum, o);
    if (lane == 0) wsum[w] = esum;
    __syncthreads();
    if (tid < 8) {
        float x = wsum[tid];
        for (int o = 4; o; o >>= 1) x += __shfl_xor_sync(0x000000ffu, x, o);
        if (tid == 0) atomicAdd(&out[(size_t)4 * Npts], x);
    }
}

// ---------------------------------------------------------------------------
extern "C" void kernel_launch(void* const* d_in, const int* in_sizes, int n_in,
                              void* d_out, int out_size) {
    (void)n_in;
    (void)out_size;
    const float* z = (const float*)d_in[0];
    const float* phi = (const float*)d_in[1];
    const float* mu = (const float*)d_in[2];
    const float* sigma = (const float*)d_in[3];
    float* out = (float*)d_out;

    const int Npts = in_sizes[0] / (VV * DD);

    const int SETUP_SMEM = (2 * DD * (DD + 1) + 2 * DD) * (int)sizeof(float);
    const int MAIN_SMEM = 106496;  // 104 KB

    cudaFuncSetAttribute(setup_kernel,
                         cudaFuncAttributeMaxDynamicSharedMemorySize, SETUP_SMEM);
    cudaFuncSetAttribute(main_kernel,
                         cudaFuncAttributeMaxDynamicSharedMemorySize, MAIN_SMEM);

    init_kernel<<<1, 1>>>(out, Npts);
    setup_kernel<<<VV * KK, DD, SETUP_SMEM>>>(phi, mu, sigma, out, Npts);

    const int bpv = (Npts + TN - 1) / TN;
    main_kernel<<<bpv, 256, MAIN_SMEM>>>(z, out, Npts);
}

// round 6
// speedup vs baseline: 2.4868x; 1.0132x over previous
#include <cuda_runtime.h>
#include <cuda_bf16.h>
#include <math.h>
#include <stdint.h>

#define VV 2
#define KK 8
#define DD 128
#define TN 128
#define LOG2PI_F 1.8378770664093453f

__device__ uint32_t g_Bfrag[VV * KK * 9216];
__device__ float g_u[VV * KK * DD];
__device__ float g_logc[VV * KK];
__device__ float g_pen[VV * KK];
__device__ int g_ticket;

__device__ __forceinline__ void split_bf16(float x, unsigned short& h, unsigned short& l) {
    __nv_bfloat16 hb = __float2bfloat16(x);
    float r = x - __bfloat162float(hb);
    __nv_bfloat16 lb = __float2bfloat16(r);
    h = __bfloat16_as_ushort(hb);
    l = __bfloat16_as_ushort(lb);
}

#define MMA16816(c, a, b)                                                      \
    asm volatile(                                                              \
        "mma.sync.aligned.m16n8k16.row.col.f32.bf16.bf16.f32 "                 \
        "{%0,%1,%2,%3}, {%4,%5,%6,%7}, {%8,%9}, {%0,%1,%2,%3};"                \
        : "+f"((c)[0]), "+f"((c)[1]), "+f"((c)[2]), "+f"((c)[3])               \
        : "r"((a)[0]), "r"((a)[1]), "r"((a)[2]), "r"((a)[3]),                  \
          "r"((b).x), "r"((b).y))

// ---------------------------------------------------------------------------
// setup: per (v,k) Cholesky, M=L^-1, u, log-consts, penalty slot, B blobs.
// Block (0): also zero out[4N] and g_ticket.
// ---------------------------------------------------------------------------
__global__ void setup_kernel(const float* __restrict__ phi,
                             const float* __restrict__ mu,
                             const float* __restrict__ sigma,
                             float* __restrict__ out, int Npts) {
    extern __shared__ float sm[];
    float (*A)[DD + 1] = (float (*)[DD + 1])sm;
    float (*M)[DD + 1] = (float (*)[DD + 1])(sm + DD * (DD + 1));
    float* red = sm + 2 * DD * (DD + 1);
    float* mus = red + DD;

    const int t = threadIdx.x;
    const int v = blockIdx.x / KK;
    const int k = blockIdx.x % KK;
    const float* S = sigma + (size_t)(v * KK + k) * DD * DD;

    if (blockIdx.x == 0 && t == 0) {
        out[(size_t)4 * Npts] = 0.0f;
        g_ticket = 0;
    }

    for (int r = 0; r < DD; r++) A[r][t] = S[r * DD + t];
    __syncthreads();

    float dg = A[t][t] + 1e-6f;
    A[t][t] = dg;
    red[t] = 1.0f / (dg + 1e-12f);
    __syncthreads();
    for (int s = 64; s > 0; s >>= 1) {
        if (t < s) red[t] += red[t + s];
        __syncthreads();
    }
    if (t == 0) g_pen[v * KK + k] = red[0];
    __syncthreads();

    for (int j = 0; j < DD; j++) {
        if (t == j) A[j][j] = sqrtf(A[j][j]);
        __syncthreads();
        float Ljj = A[j][j];
        float lij = 0.0f;
        if (t > j) {
            lij = A[t][j] / Ljj;
            A[t][j] = lij;
        }
        __syncthreads();
        if (t > j) {
#pragma unroll 4
            for (int l = j + 1; l <= t; l++)
                A[t][l] = fmaf(-lij, A[l][j], A[t][l]);
        }
        __syncthreads();
    }

    red[t] = logf(A[t][t]);
    __syncthreads();
    for (int s = 64; s > 0; s >>= 1) {
        if (t < s) red[t] += red[t + s];
        __syncthreads();
    }
    float logdet = fmaxf(2.0f * red[0], logf(1e-6f));
    __syncthreads();

    for (int r = 0; r < DD; r++) M[r][t] = 0.0f;
    __syncthreads();
    const int c = t;
    for (int j = 0; j < DD; j++) {
        float s0 = 0.0f, s1 = 0.0f, s2 = 0.0f, s3 = 0.0f;
        int jr = j & ~3;
        for (int i = 0; i < jr; i += 4) {
            s0 = fmaf(A[j][i], M[i][c], s0);
            s1 = fmaf(A[j][i + 1], M[i + 1][c], s1);
            s2 = fmaf(A[j][i + 2], M[i + 2][c], s2);
            s3 = fmaf(A[j][i + 3], M[i + 3][c], s3);
        }
        for (int i = jr; i < j; i++) s0 = fmaf(A[j][i], M[i][c], s0);
        float s = (s0 + s1) + (s2 + s3);
        if (j >= c) M[j][c] = (((j == c) ? 1.0f : 0.0f) - s) / A[j][j];
    }
    __syncthreads();

    mus[t] = mu[(size_t)(v * KK + k) * DD + t];
    __syncthreads();
    float u = 0.0f;
    for (int j = 0; j < DD; j++) u = fmaf(M[t][j], mus[j], u);
    g_u[(size_t)(v * KK + k) * DD + t] = u;

    uint32_t* blob = g_Bfrag + (size_t)(v * KK + k) * 9216;
    for (int idx = t; idx < 9216; idx += DD) {
        int reg = idx & 1;
        int lane = (idx >> 1) & 31;
        int hl = (idx >> 6) & 1;
        int ws = idx >> 7;
        int w = ws / 9;
        int s = ws - w * 9;
        int nA = (w >> 1) + 1;
        int b = (s < nA) ? w : 15 - w;
        int kb = (s < nA) ? s : s - nA;
        int col = b * 8 + (lane >> 2);
        int k0 = kb * 16 + (lane & 3) * 2 + reg * 8;
        unsigned short h0, l0, h1, l1;
        split_bf16(M[col][k0], h0, l0);
        split_bf16(M[col][k0 + 1], h1, l1);
        blob[idx] = hl ? ((uint32_t)l0 | ((uint32_t)l1 << 16))
                       : ((uint32_t)h0 | ((uint32_t)h1 << 16));
    }

    if (t == 0) {
        float pm = -3.0e38f;
        for (int i = 0; i < KK; i++) pm = fmaxf(pm, phi[v * KK + i]);
        float se = 0.0f;
        for (int i = 0; i < KK; i++) se += expf(phi[v * KK + i] - pm);
        float logpi = phi[v * KK + k] - pm - logf(se);
        g_logc[v * KK + k] = logpi - 0.5f * (float)DD * LOG2PI_F - 0.5f * logdet;
    }
}

// ---------------------------------------------------------------------------
// templated per-view mainloop: NA compile-time; pass-major MMA order in
// rb-chunks of 4 so same-accumulator HMMA distance >= 4 issues.
// ---------------------------------------------------------------------------
template <int NA>
__device__ __forceinline__ void view_mainloop(
    const uint32_t* __restrict__ Bg, const uint32_t* __restrict__ Ah,
    float* __restrict__ slab, const float* __restrict__ us,
    int w, int lane) {
    constexpr int NB = 9 - NA;
    const int tq = lane & 3;
    const int tr = lane >> 2;

    uint2 BfA[NA][2], BfB[NB][2];
    {
        const uint32_t* bc = Bg + w * 9 * 128 + lane * 2;
#pragma unroll
        for (int s = 0; s < NA; s++) {
            BfA[s][0] = *(const uint2*)(bc + (s * 2 + 0) * 64);
            BfA[s][1] = *(const uint2*)(bc + (s * 2 + 1) * 64);
        }
#pragma unroll
        for (int s = 0; s < NB; s++) {
            BfB[s][0] = *(const uint2*)(bc + ((NA + s) * 2 + 0) * 64);
            BfB[s][1] = *(const uint2*)(bc + ((NA + s) * 2 + 1) * 64);
        }
    }

    for (int comp = 0; comp < KK; comp++) {
        float accA[8][4], accB[8][4];
#pragma unroll
        for (int rb = 0; rb < 8; rb++)
#pragma unroll
            for (int r = 0; r < 4; r++) {
                accA[rb][r] = 0.0f;
                accB[rb][r] = 0.0f;
            }

#pragma unroll
        for (int kb = 0; kb < NB; kb++) {
#pragma unroll
            for (int rbc = 0; rbc < 2; rbc++) {
                uint32_t a[4][4], al[4][4];
#pragma unroll
                for (int r4 = 0; r4 < 4; r4++) {
                    const uint32_t* ap =
                        Ah + ((rbc * 4 + r4) * 8 + kb) * 128 + lane * 4;
                    uint4 av = *(const uint4*)ap;
                    uint4 lv = *(const uint4*)(ap + 8192);
                    a[r4][0] = av.x; a[r4][1] = av.y;
                    a[r4][2] = av.z; a[r4][3] = av.w;
                    al[r4][0] = lv.x; al[r4][1] = lv.y;
                    al[r4][2] = lv.z; al[r4][3] = lv.w;
                }
                // pass-major: same-acc distance = 4 HMMA issues
#pragma unroll
                for (int r4 = 0; r4 < 4; r4++)
                    MMA16816(accB[rbc * 4 + r4], a[r4], BfB[kb][0]);
                if (kb < NA) {
#pragma unroll
                    for (int r4 = 0; r4 < 4; r4++)
                        MMA16816(accA[rbc * 4 + r4], a[r4], BfA[kb][0]);
                }
#pragma unroll
                for (int r4 = 0; r4 < 4; r4++)
                    MMA16816(accB[rbc * 4 + r4], a[r4], BfB[kb][1]);
                if (kb < NA) {
#pragma unroll
                    for (int r4 = 0; r4 < 4; r4++)
                        MMA16816(accA[rbc * 4 + r4], a[r4], BfA[kb][1]);
                }
#pragma unroll
                for (int r4 = 0; r4 < 4; r4++)
                    MMA16816(accB[rbc * 4 + r4], al[r4], BfB[kb][0]);
                if (kb < NA) {
#pragma unroll
                    for (int r4 = 0; r4 < 4; r4++)
                        MMA16816(accA[rbc * 4 + r4], al[r4], BfA[kb][0]);
                }
            }
        }

        if (comp + 1 < KK) {
            const uint32_t* bc =
                Bg + (size_t)(comp + 1) * 9216 + w * 9 * 128 + lane * 2;
#pragma unroll
            for (int s = 0; s < NA; s++) {
                BfA[s][0] = *(const uint2*)(bc + (s * 2 + 0) * 64);
                BfA[s][1] = *(const uint2*)(bc + (s * 2 + 1) * 64);
            }
#pragma unroll
            for (int s = 0; s < NB; s++) {
                BfB[s][0] = *(const uint2*)(bc + ((NA + s) * 2 + 0) * 64);
                BfB[s][1] = *(const uint2*)(bc + ((NA + s) * 2 + 1) * 64);
            }
        }

        const float* uc = us + comp * DD;
        float uA0 = uc[w * 8 + tq * 2];
        float uA1 = uc[w * 8 + tq * 2 + 1];
        float uB0 = uc[(15 - w) * 8 + tq * 2];
        float uB1 = uc[(15 - w) * 8 + tq * 2 + 1];
#pragma unroll
        for (int rb = 0; rb < 8; rb++) {
            float d0 = accA[rb][0] - uA0;
            float d1 = accA[rb][1] - uA1;
            float d2 = accB[rb][0] - uB0;
            float d3 = accB[rb][1] - uB1;
            float s0 = d0 * d0 + d1 * d1 + d2 * d2 + d3 * d3;
            float e0 = accA[rb][2] - uA0;
            float e1 = accA[rb][3] - uA1;
            float e2 = accB[rb][2] - uB0;
            float e3 = accB[rb][3] - uB1;
            float s1 = e0 * e0 + e1 * e1 + e2 * e2 + e3 * e3;
            s0 += __shfl_xor_sync(0xffffffffu, s0, 1);
            s0 += __shfl_xor_sync(0xffffffffu, s0, 2);
            s1 += __shfl_xor_sync(0xffffffffu, s1, 1);
            s1 += __shfl_xor_sync(0xffffffffu, s1, 2);
            if (tq == 0) {
                slab[w * 1024 + (rb * 16 + tr) * 8 + comp] = s0;
                slab[w * 1024 + (rb * 16 + tr + 8) * 8 + comp] = s1;
            }
        }
    }
}

// ---------------------------------------------------------------------------
// main: persistent CTAs, atomic ticket over 128-pt tiles, both views fused.
// smem: Ah 32K | Al 32K | slab 32K | us 4K | mah 4K | s_tile = 104.1 KB
// ---------------------------------------------------------------------------
__global__ void __launch_bounds__(256)
main_kernel(const float* __restrict__ z, float* __restrict__ out,
            int Npts, int ntiles) {
    extern __shared__ __align__(16) unsigned char smraw[];
    uint32_t* Ah = (uint32_t*)smraw;                 // 32 KB (+ Al at +8192 u32)
    float* slab = (float*)(smraw + 65536);           // 32 KB
    float* us = (float*)(smraw + 98304);             // 4 KB
    float* mah = (float*)(smraw + 102400);           // 4 KB
    int* s_tile = (int*)(smraw + 106496);

    const int tid = threadIdx.x;
    const int w = tid >> 5;
    const int lane = tid & 31;

    if (blockIdx.x == 0 && tid == 0) {
        float p = 0.0f;
#pragma unroll
        for (int i = 0; i < VV * KK; i++) p += g_pen[i];
        out[(size_t)4 * Npts + 1] = p;
    }

    float esum = 0.0f;

    for (;;) {
        if (tid == 0) *s_tile = atomicAdd(&g_ticket, 1);
        __syncthreads();
        const int tile = *s_tile;
        if (tile >= ntiles) break;
        const int n0 = tile * TN;

        float e_prev = 0.0f;

        for (int v = 0; v < VV; v++) {
            const uint32_t* Bg = g_Bfrag + (size_t)v * KK * 9216;

            for (int i = tid; i < KK * DD; i += 256)
                us[i] = g_u[(size_t)v * KK * DD + i];

            const float* zr = z + (size_t)v * Npts * DD;
#pragma unroll
            for (int it = 0; it < 8; it++) {
                int idx = tid + it * 256;
                int p = idx >> 4;
                int oct = idx & 15;
                int n = n0 + p;
                float f[8];
                if (n < Npts) {
                    const float4* src =
                        (const float4*)(zr + (size_t)n * DD + oct * 8);
                    float4 a = src[0], b = src[1];
                    f[0] = a.x; f[1] = a.y; f[2] = a.z; f[3] = a.w;
                    f[4] = b.x; f[5] = b.y; f[6] = b.z; f[7] = b.w;
                } else {
#pragma unroll
                    for (int j = 0; j < 8; j++) f[j] = 0.0f;
                }
                int rb = p >> 4;
                int row_in = p & 15;
                int lane_row = row_in & 7;
                int rbit = row_in >> 3;
                int kb = oct >> 1;
                int khalf = oct & 1;
                int reg = (khalf << 1) | rbit;
                uint32_t base = (uint32_t)((rb * 8 + kb) * 128 + reg);
#pragma unroll
                for (int j = 0; j < 4; j++) {
                    unsigned short h0, l0, h1, l1;
                    split_bf16(f[2 * j], h0, l0);
                    split_bf16(f[2 * j + 1], h1, l1);
                    uint32_t off = base + (uint32_t)(lane_row * 4 + j) * 4;
                    Ah[off] = (uint32_t)h0 | ((uint32_t)h1 << 16);
                    Ah[off + 8192] = (uint32_t)l0 | ((uint32_t)l1 << 16);
                }
            }
            __syncthreads();

            switch (w >> 1) {
                case 0: view_mainloop<1>(Bg, Ah, slab, us, w, lane); break;
                case 1: view_mainloop<2>(Bg, Ah, slab, us, w, lane); break;
                case 2: view_mainloop<3>(Bg, Ah, slab, us, w, lane); break;
                default: view_mainloop<4>(Bg, Ah, slab, us, w, lane); break;
            }
            __syncthreads();

            for (int i = tid; i < TN * KK; i += 256) {
                float s = 0.0f;
#pragma unroll
                for (int ww = 0; ww < 8; ww++) s += slab[ww * 1024 + i];
                mah[i] = s;
            }
            __syncthreads();

            if (tid < TN) {
                int n = n0 + tid;
                if (n < Npts) {
                    float lp[KK];
                    float m = -3.0e38f;
#pragma unroll
                    for (int k = 0; k < KK; k++) {
                        lp[k] = fmaf(-0.5f, mah[tid * KK + k],
                                     g_logc[v * KK + k]);
                        m = fmaxf(m, lp[k]);
                    }
                    float se = 0.0f;
#pragma unroll
                    for (int k = 0; k < KK; k++) se += expf(lp[k] - m);
                    float e = -(m + logf(se));
                    out[(size_t)n * VV + v] = e;
                    if (v == 0) {
                        e_prev = e;
                    } else {
                        float mm = fminf(e_prev, e);
                        float a = expf(mm - e_prev);
                        float b = expf(mm - e);
                        float inv = 1.0f / (a + b);
                        size_t wb = (size_t)2 * Npts;
                        out[wb + (size_t)n * VV] = a * inv;
                        out[wb + (size_t)n * VV + 1] = b * inv;
                        esum += e_prev + e;
                    }
                }
            }
            __syncthreads();
        }
    }

    __shared__ float wsum[8];
    for (int o = 16; o; o >>= 1) esum += __shfl_xor_sync(0xffffffffu, esum, o);
    if (lane == 0) wsum[w] = esum;
    __syncthreads();
    if (tid < 8) {
        float x = wsum[tid];
        for (int o = 4; o; o >>= 1) x += __shfl_xor_sync(0x000000ffu, x, o);
        if (tid == 0) atomicAdd(&out[(size_t)4 * Npts], x);
    }
}

// ---------------------------------------------------------------------------
extern "C" void kernel_launch(void* const* d_in, const int* in_sizes, int n_in,
                              void* d_out, int out_size) {
    (void)n_in;
    (void)out_size;
    const float* z = (const float*)d_in[0];
    const float* phi = (const float*)d_in[1];
    const float* mu = (const float*)d_in[2];
    const float* sigma = (const float*)d_in[3];
    float* out = (float*)d_out;

    const int Npts = in_sizes[0] / (VV * DD);
    const int ntiles = (Npts + TN - 1) / TN;

    static int nsm = 0;
    if (nsm == 0) {
        int dev = 0;
        cudaGetDevice(&dev);
        cudaDeviceGetAttribute(&nsm, cudaDevAttrMultiProcessorCount, dev);
        if (nsm <= 0) nsm = 148;
    }

    const int SETUP_SMEM = (2 * DD * (DD + 1) + 2 * DD) * (int)sizeof(float);
    const int MAIN_SMEM = 106496 + 16;

    cudaFuncSetAttribute(setup_kernel,
                         cudaFuncAttributeMaxDynamicSharedMemorySize, SETUP_SMEM);
    cudaFuncSetAttribute(main_kernel,
                         cudaFuncAttributeMaxDynamicSharedMemorySize, MAIN_SMEM);

    setup_kernel<<<VV * KK, DD, SETUP_SMEM>>>(phi, mu, sigma, out, Npts);
    main_kernel<<<nsm, 256, MAIN_SMEM>>>(z, out, Npts, ntiles);
}

// round 7
// speedup vs baseline: 2.6202x; 1.0536x over previous
#include <cuda_runtime.h>
#include <cuda_bf16.h>
#include <math.h>
#include <stdint.h>

#define VV 2
#define KK 8
#define DD 128
#define TN 128
#define LOG2PI_F 1.8378770664093453f

__device__ uint32_t g_Bfrag[VV * KK * 9216];
__device__ float g_u[VV * KK * DD];
__device__ float g_logc[VV * KK];
__device__ float g_pen[VV * KK];
__device__ int g_ticket;

__device__ __forceinline__ void split_bf16(float x, unsigned short& h, unsigned short& l) {
    __nv_bfloat16 hb = __float2bfloat16(x);
    float r = x - __bfloat162float(hb);
    __nv_bfloat16 lb = __float2bfloat16(r);
    h = __bfloat16_as_ushort(hb);
    l = __bfloat16_as_ushort(lb);
}

#define MMA16816(c, a, b)                                                      \
    asm volatile(                                                              \
        "mma.sync.aligned.m16n8k16.row.col.f32.bf16.bf16.f32 "                 \
        "{%0,%1,%2,%3}, {%4,%5,%6,%7}, {%8,%9}, {%0,%1,%2,%3};"                \
        : "+f"((c)[0]), "+f"((c)[1]), "+f"((c)[2]), "+f"((c)[3])               \
        : "r"((a)[0]), "r"((a)[1]), "r"((a)[2]), "r"((a)[3]),                  \
          "r"((b).x), "r"((b).y))

// ---------------------------------------------------------------------------
// setup: per (v,k) Cholesky, M=L^-1, u, log-consts, penalty, B blobs.
// 256 threads: Cholesky update split 2-way over l; loads/blob over 256.
// ---------------------------------------------------------------------------
__global__ void __launch_bounds__(256)
setup_kernel(const float* __restrict__ phi,
             const float* __restrict__ mu,
             const float* __restrict__ sigma,
             float* __restrict__ out, int Npts) {
    extern __shared__ float sm[];
    float (*A)[DD + 1] = (float (*)[DD + 1])sm;
    float (*M)[DD + 1] = (float (*)[DD + 1])(sm + DD * (DD + 1));
    float* red = sm + 2 * DD * (DD + 1);
    float* mus = red + DD;

    const int tid = threadIdx.x;
    const int t = tid & 127;          // row/col role
    const int h = tid >> 7;           // half
    const int v = blockIdx.x / KK;
    const int k = blockIdx.x % KK;
    const float* S = sigma + (size_t)(v * KK + k) * DD * DD;

    if (blockIdx.x == 0 && tid == 0) {
        out[(size_t)4 * Npts] = 0.0f;
        g_ticket = 0;
    }

    for (int idx = tid; idx < DD * DD; idx += 256)
        A[idx >> 7][idx & 127] = S[idx];
    __syncthreads();

    if (tid < DD) {
        float dg = A[tid][tid] + 1e-6f;
        A[tid][tid] = dg;
        red[tid] = 1.0f / (dg + 1e-12f);
    }
    __syncthreads();
    for (int s = 64; s > 0; s >>= 1) {
        if (tid < s) red[tid] += red[tid + s];
        __syncthreads();
    }
    if (tid == 0) g_pen[v * KK + k] = red[0];
    __syncthreads();

    // right-looking Cholesky; update split 2-way over l
    for (int j = 0; j < DD; j++) {
        if (tid == j) A[j][j] = sqrtf(A[j][j]);
        __syncthreads();
        if (tid < DD && tid > j) A[tid][j] = A[tid][j] / A[j][j];
        __syncthreads();
        if (t > j) {
            float lij = A[t][j];
#pragma unroll 4
            for (int l = j + 1 + h; l <= t; l += 2)
                A[t][l] = fmaf(-lij, A[l][j], A[t][l]);
        }
        __syncthreads();
    }

    if (tid < DD) red[tid] = logf(A[tid][tid]);
    __syncthreads();
    for (int s = 64; s > 0; s >>= 1) {
        if (tid < s) red[tid] += red[tid + s];
        __syncthreads();
    }
    float logdet = fmaxf(2.0f * red[0], logf(1e-6f));
    __syncthreads();

    for (int idx = tid; idx < DD * DD; idx += 256)
        M[idx >> 7][idx & 127] = 0.0f;
    __syncthreads();
    if (tid < DD) {
        const int c = tid;
        for (int j = 0; j < DD; j++) {
            float s0 = 0.0f, s1 = 0.0f, s2 = 0.0f, s3 = 0.0f;
            int jr = j & ~3;
            for (int i = 0; i < jr; i += 4) {
                s0 = fmaf(A[j][i], M[i][c], s0);
                s1 = fmaf(A[j][i + 1], M[i + 1][c], s1);
                s2 = fmaf(A[j][i + 2], M[i + 2][c], s2);
                s3 = fmaf(A[j][i + 3], M[i + 3][c], s3);
            }
            for (int i = jr; i < j; i++) s0 = fmaf(A[j][i], M[i][c], s0);
            float s = (s0 + s1) + (s2 + s3);
            if (j >= c) M[j][c] = (((j == c) ? 1.0f : 0.0f) - s) / A[j][j];
        }
    }
    __syncthreads();

    if (tid < DD) mus[tid] = mu[(size_t)(v * KK + k) * DD + tid];
    __syncthreads();
    if (tid < DD) {
        float u = 0.0f;
        for (int j = 0; j < DD; j++) u = fmaf(M[tid][j], mus[j], u);
        g_u[(size_t)(v * KK + k) * DD + tid] = u;
    }

    uint32_t* blob = g_Bfrag + (size_t)(v * KK + k) * 9216;
    for (int idx = tid; idx < 9216; idx += 256) {
        int reg = idx & 1;
        int lane = (idx >> 1) & 31;
        int hl = (idx >> 6) & 1;
        int ws = idx >> 7;
        int w = ws / 9;
        int s = ws - w * 9;
        int nA = (w >> 1) + 1;
        int b = (s < nA) ? w : 15 - w;
        int kb = (s < nA) ? s : s - nA;
        int col = b * 8 + (lane >> 2);
        int k0 = kb * 16 + (lane & 3) * 2 + reg * 8;
        unsigned short h0, l0, h1, l1;
        split_bf16(M[col][k0], h0, l0);
        split_bf16(M[col][k0 + 1], h1, l1);
        blob[idx] = hl ? ((uint32_t)l0 | ((uint32_t)l1 << 16))
                       : ((uint32_t)h0 | ((uint32_t)h1 << 16));
    }

    if (tid == 0) {
        float pm = -3.0e38f;
        for (int i = 0; i < KK; i++) pm = fmaxf(pm, phi[v * KK + i]);
        float se = 0.0f;
        for (int i = 0; i < KK; i++) se += expf(phi[v * KK + i] - pm);
        float logpi = phi[v * KK + k] - pm - logf(se);
        g_logc[v * KK + k] = logpi - 0.5f * (float)DD * LOG2PI_F - 0.5f * logdet;
    }
}

// ---------------------------------------------------------------------------
// templated per-view mainloop (unchanged from R6)
// ---------------------------------------------------------------------------
template <int NA>
__device__ __forceinline__ void view_mainloop(
    const uint32_t* __restrict__ Bg, const uint32_t* __restrict__ Ah,
    float* __restrict__ slab, const float* __restrict__ us,
    int w, int lane) {
    constexpr int NB = 9 - NA;
    const int tq = lane & 3;
    const int tr = lane >> 2;

    uint2 BfA[NA][2], BfB[NB][2];
    {
        const uint32_t* bc = Bg + w * 9 * 128 + lane * 2;
#pragma unroll
        for (int s = 0; s < NA; s++) {
            BfA[s][0] = *(const uint2*)(bc + (s * 2 + 0) * 64);
            BfA[s][1] = *(const uint2*)(bc + (s * 2 + 1) * 64);
        }
#pragma unroll
        for (int s = 0; s < NB; s++) {
            BfB[s][0] = *(const uint2*)(bc + ((NA + s) * 2 + 0) * 64);
            BfB[s][1] = *(const uint2*)(bc + ((NA + s) * 2 + 1) * 64);
        }
    }

    for (int comp = 0; comp < KK; comp++) {
        float accA[8][4], accB[8][4];
#pragma unroll
        for (int rb = 0; rb < 8; rb++)
#pragma unroll
            for (int r = 0; r < 4; r++) {
                accA[rb][r] = 0.0f;
                accB[rb][r] = 0.0f;
            }

#pragma unroll
        for (int kb = 0; kb < NB; kb++) {
#pragma unroll
            for (int rbc = 0; rbc < 2; rbc++) {
                uint32_t a[4][4], al[4][4];
#pragma unroll
                for (int r4 = 0; r4 < 4; r4++) {
                    const uint32_t* ap =
                        Ah + ((rbc * 4 + r4) * 8 + kb) * 128 + lane * 4;
                    uint4 av = *(const uint4*)ap;
                    uint4 lv = *(const uint4*)(ap + 8192);
                    a[r4][0] = av.x; a[r4][1] = av.y;
                    a[r4][2] = av.z; a[r4][3] = av.w;
                    al[r4][0] = lv.x; al[r4][1] = lv.y;
                    al[r4][2] = lv.z; al[r4][3] = lv.w;
                }
#pragma unroll
                for (int r4 = 0; r4 < 4; r4++)
                    MMA16816(accB[rbc * 4 + r4], a[r4], BfB[kb][0]);
                if (kb < NA) {
#pragma unroll
                    for (int r4 = 0; r4 < 4; r4++)
                        MMA16816(accA[rbc * 4 + r4], a[r4], BfA[kb][0]);
                }
#pragma unroll
                for (int r4 = 0; r4 < 4; r4++)
                    MMA16816(accB[rbc * 4 + r4], a[r4], BfB[kb][1]);
                if (kb < NA) {
#pragma unroll
                    for (int r4 = 0; r4 < 4; r4++)
                        MMA16816(accA[rbc * 4 + r4], a[r4], BfA[kb][1]);
                }
#pragma unroll
                for (int r4 = 0; r4 < 4; r4++)
                    MMA16816(accB[rbc * 4 + r4], al[r4], BfB[kb][0]);
                if (kb < NA) {
#pragma unroll
                    for (int r4 = 0; r4 < 4; r4++)
                        MMA16816(accA[rbc * 4 + r4], al[r4], BfA[kb][0]);
                }
            }
        }

        if (comp + 1 < KK) {
            const uint32_t* bc =
                Bg + (size_t)(comp + 1) * 9216 + w * 9 * 128 + lane * 2;
#pragma unroll
            for (int s = 0; s < NA; s++) {
                BfA[s][0] = *(const uint2*)(bc + (s * 2 + 0) * 64);
                BfA[s][1] = *(const uint2*)(bc + (s * 2 + 1) * 64);
            }
#pragma unroll
            for (int s = 0; s < NB; s++) {
                BfB[s][0] = *(const uint2*)(bc + ((NA + s) * 2 + 0) * 64);
                BfB[s][1] = *(const uint2*)(bc + ((NA + s) * 2 + 1) * 64);
            }
        }

        const float* uc = us + comp * DD;
        float uA0 = uc[w * 8 + tq * 2];
        float uA1 = uc[w * 8 + tq * 2 + 1];
        float uB0 = uc[(15 - w) * 8 + tq * 2];
        float uB1 = uc[(15 - w) * 8 + tq * 2 + 1];
#pragma unroll
        for (int rb = 0; rb < 8; rb++) {
            float d0 = accA[rb][0] - uA0;
            float d1 = accA[rb][1] - uA1;
            float d2 = accB[rb][0] - uB0;
            float d3 = accB[rb][1] - uB1;
            float s0 = d0 * d0 + d1 * d1 + d2 * d2 + d3 * d3;
            float e0 = accA[rb][2] - uA0;
            float e1 = accA[rb][3] - uA1;
            float e2 = accB[rb][2] - uB0;
            float e3 = accB[rb][3] - uB1;
            float s1 = e0 * e0 + e1 * e1 + e2 * e2 + e3 * e3;
            s0 += __shfl_xor_sync(0xffffffffu, s0, 1);
            s0 += __shfl_xor_sync(0xffffffffu, s0, 2);
            s1 += __shfl_xor_sync(0xffffffffu, s1, 1);
            s1 += __shfl_xor_sync(0xffffffffu, s1, 2);
            if (tq == 0) {
                slab[w * 1024 + (rb * 16 + tr) * 8 + comp] = s0;
                slab[w * 1024 + (rb * 16 + tr + 8) * 8 + comp] = s1;
            }
        }
    }
}

// ---------------------------------------------------------------------------
// main: persistent, 2 CTAs/SM, atomic ticket over 128-pt tiles, views fused.
// dyn smem: Ah 32K | Al 32K | slab 32K | us 4K | mah 4K = 104 KB (x2 per SM)
// ---------------------------------------------------------------------------
__global__ void __launch_bounds__(256)
main_kernel(const float* __restrict__ z, float* __restrict__ out,
            int Npts, int ntiles) {
    extern __shared__ __align__(16) unsigned char smraw[];
    uint32_t* Ah = (uint32_t*)smraw;                 // 32 KB (+ Al at +8192 u32)
    float* slab = (float*)(smraw + 65536);           // 32 KB
    float* us = (float*)(smraw + 98304);             // 4 KB
    float* mah = (float*)(smraw + 102400);           // 4 KB
    __shared__ int s_tile;
    __shared__ float wsum[8];

    const int tid = threadIdx.x;
    const int w = tid >> 5;
    const int lane = tid & 31;

    if (blockIdx.x == 0 && tid == 0) {
        float p = 0.0f;
#pragma unroll
        for (int i = 0; i < VV * KK; i++) p += g_pen[i];
        out[(size_t)4 * Npts + 1] = p;
    }

    float esum = 0.0f;

    for (;;) {
        if (tid == 0) s_tile = atomicAdd(&g_ticket, 1);
        __syncthreads();
        const int tile = s_tile;
        if (tile >= ntiles) break;
        const int n0 = tile * TN;

        float e_prev = 0.0f;

        for (int v = 0; v < VV; v++) {
            const uint32_t* Bg = g_Bfrag + (size_t)v * KK * 9216;

            for (int i = tid; i < KK * DD; i += 256)
                us[i] = g_u[(size_t)v * KK * DD + i];

            const float* zr = z + (size_t)v * Npts * DD;
#pragma unroll
            for (int it = 0; it < 8; it++) {
                int idx = tid + it * 256;
                int p = idx >> 4;
                int oct = idx & 15;
                int n = n0 + p;
                float f[8];
                if (n < Npts) {
                    const float4* src =
                        (const float4*)(zr + (size_t)n * DD + oct * 8);
                    float4 a = src[0], b = src[1];
                    f[0] = a.x; f[1] = a.y; f[2] = a.z; f[3] = a.w;
                    f[4] = b.x; f[5] = b.y; f[6] = b.z; f[7] = b.w;
                } else {
#pragma unroll
                    for (int j = 0; j < 8; j++) f[j] = 0.0f;
                }
                int rb = p >> 4;
                int row_in = p & 15;
                int lane_row = row_in & 7;
                int rbit = row_in >> 3;
                int kb = oct >> 1;
                int khalf = oct & 1;
                int reg = (khalf << 1) | rbit;
                uint32_t base = (uint32_t)((rb * 8 + kb) * 128 + reg);
#pragma unroll
                for (int j = 0; j < 4; j++) {
                    unsigned short h0, l0, h1, l1;
                    split_bf16(f[2 * j], h0, l0);
                    split_bf16(f[2 * j + 1], h1, l1);
                    uint32_t off = base + (uint32_t)(lane_row * 4 + j) * 4;
                    Ah[off] = (uint32_t)h0 | ((uint32_t)h1 << 16);
                    Ah[off + 8192] = (uint32_t)l0 | ((uint32_t)l1 << 16);
                }
            }
            __syncthreads();

            switch (w >> 1) {
                case 0: view_mainloop<1>(Bg, Ah, slab, us, w, lane); break;
                case 1: view_mainloop<2>(Bg, Ah, slab, us, w, lane); break;
                case 2: view_mainloop<3>(Bg, Ah, slab, us, w, lane); break;
                default: view_mainloop<4>(Bg, Ah, slab, us, w, lane); break;
            }
            __syncthreads();

            for (int i = tid; i < TN * KK; i += 256) {
                float s = 0.0f;
#pragma unroll
                for (int ww = 0; ww < 8; ww++) s += slab[ww * 1024 + i];
                mah[i] = s;
            }
            __syncthreads();

            if (tid < TN) {
                int n = n0 + tid;
                if (n < Npts) {
                    float lp[KK];
                    float m = -3.0e38f;
#pragma unroll
                    for (int k = 0; k < KK; k++) {
                        lp[k] = fmaf(-0.5f, mah[tid * KK + k],
                                     g_logc[v * KK + k]);
                        m = fmaxf(m, lp[k]);
                    }
                    float se = 0.0f;
#pragma unroll
                    for (int k = 0; k < KK; k++) se += expf(lp[k] - m);
                    float e = -(m + logf(se));
                    out[(size_t)n * VV + v] = e;
                    if (v == 0) {
                        e_prev = e;
                    } else {
                        float mm = fminf(e_prev, e);
                        float a = expf(mm - e_prev);
                        float b = expf(mm - e);
                        float inv = 1.0f / (a + b);
                        size_t wb = (size_t)2 * Npts;
                        out[wb + (size_t)n * VV] = a * inv;
                        out[wb + (size_t)n * VV + 1] = b * inv;
                        esum += e_prev + e;
                    }
                }
            }
            __syncthreads();
        }
    }

    for (int o = 16; o; o >>= 1) esum += __shfl_xor_sync(0xffffffffu, esum, o);
    if (lane == 0) wsum[w] = esum;
    __syncthreads();
    if (tid < 8) {
        float x = wsum[tid];
        for (int o = 4; o; o >>= 1) x += __shfl_xor_sync(0x000000ffu, x, o);
        if (tid == 0) atomicAdd(&out[(size_t)4 * Npts], x);
    }
}

// ---------------------------------------------------------------------------
extern "C" void kernel_launch(void* const* d_in, const int* in_sizes, int n_in,
                              void* d_out, int out_size) {
    (void)n_in;
    (void)out_size;
    const float* z = (const float*)d_in[0];
    const float* phi = (const float*)d_in[1];
    const float* mu = (const float*)d_in[2];
    const float* sigma = (const float*)d_in[3];
    float* out = (float*)d_out;

    const int Npts = in_sizes[0] / (VV * DD);
    const int ntiles = (Npts + TN - 1) / TN;

    static int nsm = 0;
    if (nsm == 0) {
        int dev = 0;
        cudaGetDevice(&dev);
        cudaDeviceGetAttribute(&nsm, cudaDevAttrMultiProcessorCount, dev);
        if (nsm <= 0) nsm = 148;
    }

    const int SETUP_SMEM = (2 * DD * (DD + 1) + 2 * DD) * (int)sizeof(float);
    const int MAIN_SMEM = 106496;  // 104 KB -> 2 CTAs/SM

    cudaFuncSetAttribute(setup_kernel,
                         cudaFuncAttributeMaxDynamicSharedMemorySize, SETUP_SMEM);
    cudaFuncSetAttribute(main_kernel,
                         cudaFuncAttributeMaxDynamicSharedMemorySize, MAIN_SMEM);

    setup_kernel<<<VV * KK, 256, SETUP_SMEM>>>(phi, mu, sigma, out, Npts);

    int grid = 2 * nsm;
    if (grid > ntiles) grid = ntiles;
    main_kernel<<<grid, 256, MAIN_SMEM>>>(z, out, Npts, ntiles);
}

// round 8
// speedup vs baseline: 3.2004x; 1.2214x over previous
#include <cuda_runtime.h>
#include <cuda_bf16.h>
#include <math.h>
#include <stdint.h>

#define VV 2
#define KK 8
#define DD 128
#define TN 128
#define LOG2PI_F 1.8378770664093453f

__device__ uint32_t g_Bfrag[VV * KK * 9216];
__device__ float g_u[VV * KK * DD];
__device__ float g_logc[VV * KK];
__device__ float g_pen[VV * KK];
__device__ int g_ticket;

__device__ __forceinline__ void split_bf16(float x, unsigned short& h, unsigned short& l) {
    __nv_bfloat16 hb = __float2bfloat16(x);
    float r = x - __bfloat162float(hb);
    __nv_bfloat16 lb = __float2bfloat16(r);
    h = __bfloat16_as_ushort(hb);
    l = __bfloat16_as_ushort(lb);
}

#define MMA16816(c, a, b)                                                      \
    asm volatile(                                                              \
        "mma.sync.aligned.m16n8k16.row.col.f32.bf16.bf16.f32 "                 \
        "{%0,%1,%2,%3}, {%4,%5,%6,%7}, {%8,%9}, {%0,%1,%2,%3};"                \
        : "+f"((c)[0]), "+f"((c)[1]), "+f"((c)[2]), "+f"((c)[3])               \
        : "r"((a)[0]), "r"((a)[1]), "r"((a)[2]), "r"((a)[3]),                  \
          "r"((b).x), "r"((b).y))

// ---------------------------------------------------------------------------
// setup: Cholesky + BLOCKED triangular inverse (4x 32x32 diag in parallel,
// then dense GEMM waves for off-diagonal blocks), u, log-consts, B blobs.
// ---------------------------------------------------------------------------
__global__ void __launch_bounds__(256)
setup_kernel(const float* __restrict__ phi,
             const float* __restrict__ mu,
             const float* __restrict__ sigma,
             float* __restrict__ out, int Npts) {
    extern __shared__ float sm[];
    float (*A)[DD + 1] = (float (*)[DD + 1])sm;
    float (*M)[DD + 1] = (float (*)[DD + 1])(sm + DD * (DD + 1));
    float* red = sm + 2 * DD * (DD + 1);
    float* mus = red + DD;
    float* Tb = mus + DD;            // 3 * 32 * 33 floats

    const int tid = threadIdx.x;
    const int t = tid & 127;
    const int h = tid >> 7;
    const int v = blockIdx.x / KK;
    const int k = blockIdx.x % KK;
    const float* S = sigma + (size_t)(v * KK + k) * DD * DD;

    if (blockIdx.x == 0 && tid == 0) {
        out[(size_t)4 * Npts] = 0.0f;
        g_ticket = 0;
    }

    for (int idx = tid; idx < DD * DD; idx += 256)
        A[idx >> 7][idx & 127] = S[idx];
    __syncthreads();

    if (tid < DD) {
        float dg = A[tid][tid] + 1e-6f;
        A[tid][tid] = dg;
        red[tid] = 1.0f / (dg + 1e-12f);
    }
    __syncthreads();
    for (int s = 64; s > 0; s >>= 1) {
        if (tid < s) red[tid] += red[tid + s];
        __syncthreads();
    }
    if (tid == 0) g_pen[v * KK + k] = red[0];
    __syncthreads();

    // right-looking Cholesky; rank-1 update split 2-way over l
    for (int j = 0; j < DD; j++) {
        if (tid == j) A[j][j] = sqrtf(A[j][j]);
        __syncthreads();
        if (tid < DD && tid > j) A[tid][j] = A[tid][j] / A[j][j];
        __syncthreads();
        if (t > j) {
            float lij = A[t][j];
#pragma unroll 4
            for (int l = j + 1 + h; l <= t; l += 2)
                A[t][l] = fmaf(-lij, A[l][j], A[t][l]);
        }
        __syncthreads();
    }

    if (tid < DD) red[tid] = logf(A[tid][tid]);
    __syncthreads();
    for (int s = 64; s > 0; s >>= 1) {
        if (tid < s) red[tid] += red[tid + s];
        __syncthreads();
    }
    float logdet = fmaxf(2.0f * red[0], logf(1e-6f));
    __syncthreads();

    // ---- blocked triangular inverse: M = L^{-1} ----
    for (int idx = tid; idx < DD * DD; idx += 256)
        M[idx >> 7][idx & 127] = 0.0f;
    __syncthreads();

    // Phase B: invert 4 diagonal 32x32 blocks (one column per thread)
    if (tid < DD) {
        const int q = tid >> 5;
        const int c = tid & 31;
        const int base = q * 32;
        for (int j = c; j < 32; j++) {
            float s = 0.0f;
            for (int i = c; i < j; i++)
                s = fmaf(A[base + j][base + i], M[base + i][base + c], s);
            M[base + j][base + c] =
                (((j == c) ? 1.0f : 0.0f) - s) / A[base + j][base + j];
        }
    }
    __syncthreads();

    // Phase C: off-diagonal waves d=1..3:  M_pq = -M_pp * (sum_r L_pr M_rq)
    {
        const int row = tid >> 3;          // 0..31
        const int c0 = (tid & 7) * 4;      // 0,4,...,28
        for (int d = 1; d < 4; d++) {
            const int nb = 4 - d;
            // GEMM1: T_b = sum_{r=q}^{p-1} L_pr M_rq
            for (int b = 0; b < nb; b++) {
                const int p = b + d, q = b;
                float s0 = 0.0f, s1 = 0.0f, s2 = 0.0f, s3 = 0.0f;
                for (int r = q; r < p; r++) {
#pragma unroll 8
                    for (int i = 0; i < 32; i++) {
                        float a = A[p * 32 + row][r * 32 + i];
                        const float* mr = &M[r * 32 + i][q * 32 + c0];
                        s0 = fmaf(a, mr[0], s0);
                        s1 = fmaf(a, mr[1], s1);
                        s2 = fmaf(a, mr[2], s2);
                        s3 = fmaf(a, mr[3], s3);
                    }
                }
                float* tr = &Tb[b * 1056 + row * 33 + c0];
                tr[0] = s0; tr[1] = s1; tr[2] = s2; tr[3] = s3;
            }
            __syncthreads();
            // GEMM2: M_pq = -M_pp * T_b   (M_pp lower-triangular: i <= row)
            for (int b = 0; b < nb; b++) {
                const int p = b + d, q = b;
                float s0 = 0.0f, s1 = 0.0f, s2 = 0.0f, s3 = 0.0f;
                for (int i = 0; i <= row; i++) {
                    float a = M[p * 32 + row][p * 32 + i];
                    const float* tr = &Tb[b * 1056 + i * 33 + c0];
                    s0 = fmaf(a, tr[0], s0);
                    s1 = fmaf(a, tr[1], s1);
                    s2 = fmaf(a, tr[2], s2);
                    s3 = fmaf(a, tr[3], s3);
                }
                float* mr = &M[p * 32 + row][q * 32 + c0];
                mr[0] = -s0; mr[1] = -s1; mr[2] = -s2; mr[3] = -s3;
            }
            __syncthreads();
        }
    }

    if (tid < DD) mus[tid] = mu[(size_t)(v * KK + k) * DD + tid];
    __syncthreads();
    if (tid < DD) {
        float u = 0.0f;
        for (int j = 0; j < DD; j++) u = fmaf(M[tid][j], mus[j], u);
        g_u[(size_t)(v * KK + k) * DD + tid] = u;
    }

    uint32_t* blob = g_Bfrag + (size_t)(v * KK + k) * 9216;
    for (int idx = tid; idx < 9216; idx += 256) {
        int reg = idx & 1;
        int lane = (idx >> 1) & 31;
        int hl = (idx >> 6) & 1;
        int ws = idx >> 7;
        int w = ws / 9;
        int s = ws - w * 9;
        int nA = (w >> 1) + 1;
        int b = (s < nA) ? w : 15 - w;
        int kb = (s < nA) ? s : s - nA;
        int col = b * 8 + (lane >> 2);
        int k0 = kb * 16 + (lane & 3) * 2 + reg * 8;
        unsigned short h0, l0, h1, l1;
        split_bf16(M[col][k0], h0, l0);
        split_bf16(M[col][k0 + 1], h1, l1);
        blob[idx] = hl ? ((uint32_t)l0 | ((uint32_t)l1 << 16))
                       : ((uint32_t)h0 | ((uint32_t)h1 << 16));
    }

    if (tid == 0) {
        float pm = -3.0e38f;
        for (int i = 0; i < KK; i++) pm = fmaxf(pm, phi[v * KK + i]);
        float se = 0.0f;
        for (int i = 0; i < KK; i++) se += expf(phi[v * KK + i] - pm);
        float logpi = phi[v * KK + k] - pm - logf(se);
        g_logc[v * KK + k] = logpi - 0.5f * (float)DD * LOG2PI_F - 0.5f * logdet;
    }
}

// ---------------------------------------------------------------------------
// templated per-view mainloop (unchanged from R7)
// ---------------------------------------------------------------------------
template <int NA>
__device__ __forceinline__ void view_mainloop(
    const uint32_t* __restrict__ Bg, const uint32_t* __restrict__ Ah,
    float* __restrict__ slab, const float* __restrict__ us,
    int w, int lane) {
    constexpr int NB = 9 - NA;
    const int tq = lane & 3;
    const int tr = lane >> 2;

    uint2 BfA[NA][2], BfB[NB][2];
    {
        const uint32_t* bc = Bg + w * 9 * 128 + lane * 2;
#pragma unroll
        for (int s = 0; s < NA; s++) {
            BfA[s][0] = *(const uint2*)(bc + (s * 2 + 0) * 64);
            BfA[s][1] = *(const uint2*)(bc + (s * 2 + 1) * 64);
        }
#pragma unroll
        for (int s = 0; s < NB; s++) {
            BfB[s][0] = *(const uint2*)(bc + ((NA + s) * 2 + 0) * 64);
            BfB[s][1] = *(const uint2*)(bc + ((NA + s) * 2 + 1) * 64);
        }
    }

    for (int comp = 0; comp < KK; comp++) {
        float accA[8][4], accB[8][4];
#pragma unroll
        for (int rb = 0; rb < 8; rb++)
#pragma unroll
            for (int r = 0; r < 4; r++) {
                accA[rb][r] = 0.0f;
                accB[rb][r] = 0.0f;
            }

#pragma unroll
        for (int kb = 0; kb < NB; kb++) {
#pragma unroll
            for (int rbc = 0; rbc < 2; rbc++) {
                uint32_t a[4][4], al[4][4];
#pragma unroll
                for (int r4 = 0; r4 < 4; r4++) {
                    const uint32_t* ap =
                        Ah + ((rbc * 4 + r4) * 8 + kb) * 128 + lane * 4;
                    uint4 av = *(const uint4*)ap;
                    uint4 lv = *(const uint4*)(ap + 8192);
                    a[r4][0] = av.x; a[r4][1] = av.y;
                    a[r4][2] = av.z; a[r4][3] = av.w;
                    al[r4][0] = lv.x; al[r4][1] = lv.y;
                    al[r4][2] = lv.z; al[r4][3] = lv.w;
                }
#pragma unroll
                for (int r4 = 0; r4 < 4; r4++)
                    MMA16816(accB[rbc * 4 + r4], a[r4], BfB[kb][0]);
                if (kb < NA) {
#pragma unroll
                    for (int r4 = 0; r4 < 4; r4++)
                        MMA16816(accA[rbc * 4 + r4], a[r4], BfA[kb][0]);
                }
#pragma unroll
                for (int r4 = 0; r4 < 4; r4++)
                    MMA16816(accB[rbc * 4 + r4], a[r4], BfB[kb][1]);
                if (kb < NA) {
#pragma unroll
                    for (int r4 = 0; r4 < 4; r4++)
                        MMA16816(accA[rbc * 4 + r4], a[r4], BfA[kb][1]);
                }
#pragma unroll
                for (int r4 = 0; r4 < 4; r4++)
                    MMA16816(accB[rbc * 4 + r4], al[r4], BfB[kb][0]);
                if (kb < NA) {
#pragma unroll
                    for (int r4 = 0; r4 < 4; r4++)
                        MMA16816(accA[rbc * 4 + r4], al[r4], BfA[kb][0]);
                }
            }
        }

        if (comp + 1 < KK) {
            const uint32_t* bc =
                Bg + (size_t)(comp + 1) * 9216 + w * 9 * 128 + lane * 2;
#pragma unroll
            for (int s = 0; s < NA; s++) {
                BfA[s][0] = *(const uint2*)(bc + (s * 2 + 0) * 64);
                BfA[s][1] = *(const uint2*)(bc + (s * 2 + 1) * 64);
            }
#pragma unroll
            for (int s = 0; s < NB; s++) {
                BfB[s][0] = *(const uint2*)(bc + ((NA + s) * 2 + 0) * 64);
                BfB[s][1] = *(const uint2*)(bc + ((NA + s) * 2 + 1) * 64);
            }
        }

        const float* uc = us + comp * DD;
        float uA0 = uc[w * 8 + tq * 2];
        float uA1 = uc[w * 8 + tq * 2 + 1];
        float uB0 = uc[(15 - w) * 8 + tq * 2];
        float uB1 = uc[(15 - w) * 8 + tq * 2 + 1];
#pragma unroll
        for (int rb = 0; rb < 8; rb++) {
            float d0 = accA[rb][0] - uA0;
            float d1 = accA[rb][1] - uA1;
            float d2 = accB[rb][0] - uB0;
            float d3 = accB[rb][1] - uB1;
            float s0 = d0 * d0 + d1 * d1 + d2 * d2 + d3 * d3;
            float e0 = accA[rb][2] - uA0;
            float e1 = accA[rb][3] - uA1;
            float e2 = accB[rb][2] - uB0;
            float e3 = accB[rb][3] - uB1;
            float s1 = e0 * e0 + e1 * e1 + e2 * e2 + e3 * e3;
            s0 += __shfl_xor_sync(0xffffffffu, s0, 1);
            s0 += __shfl_xor_sync(0xffffffffu, s0, 2);
            s1 += __shfl_xor_sync(0xffffffffu, s1, 1);
            s1 += __shfl_xor_sync(0xffffffffu, s1, 2);
            if (tq == 0) {
                slab[w * 1024 + (rb * 16 + tr) * 8 + comp] = s0;
                slab[w * 1024 + (rb * 16 + tr + 8) * 8 + comp] = s1;
            }
        }
    }
}

// ---------------------------------------------------------------------------
// main: persistent, atomic ticket, views fused (unchanged from R7)
// ---------------------------------------------------------------------------
__global__ void __launch_bounds__(256)
main_kernel(const float* __restrict__ z, float* __restrict__ out,
            int Npts, int ntiles) {
    extern __shared__ __align__(16) unsigned char smraw[];
    uint32_t* Ah = (uint32_t*)smraw;
    float* slab = (float*)(smraw + 65536);
    float* us = (float*)(smraw + 98304);
    float* mah = (float*)(smraw + 102400);
    __shared__ int s_tile;
    __shared__ float wsum[8];

    const int tid = threadIdx.x;
    const int w = tid >> 5;
    const int lane = tid & 31;

    if (blockIdx.x == 0 && tid == 0) {
        float p = 0.0f;
#pragma unroll
        for (int i = 0; i < VV * KK; i++) p += g_pen[i];
        out[(size_t)4 * Npts + 1] = p;
    }

    float esum = 0.0f;

    for (;;) {
        if (tid == 0) s_tile = atomicAdd(&g_ticket, 1);
        __syncthreads();
        const int tile = s_tile;
        if (tile >= ntiles) break;
        const int n0 = tile * TN;

        float e_prev = 0.0f;

        for (int v = 0; v < VV; v++) {
            const uint32_t* Bg = g_Bfrag + (size_t)v * KK * 9216;

            for (int i = tid; i < KK * DD; i += 256)
                us[i] = g_u[(size_t)v * KK * DD + i];

            const float* zr = z + (size_t)v * Npts * DD;
#pragma unroll
            for (int it = 0; it < 8; it++) {
                int idx = tid + it * 256;
                int p = idx >> 4;
                int oct = idx & 15;
                int n = n0 + p;
                float f[8];
                if (n < Npts) {
                    const float4* src =
                        (const float4*)(zr + (size_t)n * DD + oct * 8);
                    float4 a = src[0], b = src[1];
                    f[0] = a.x; f[1] = a.y; f[2] = a.z; f[3] = a.w;
                    f[4] = b.x; f[5] = b.y; f[6] = b.z; f[7] = b.w;
                } else {
#pragma unroll
                    for (int j = 0; j < 8; j++) f[j] = 0.0f;
                }
                int rb = p >> 4;
                int row_in = p & 15;
                int lane_row = row_in & 7;
                int rbit = row_in >> 3;
                int kb = oct >> 1;
                int khalf = oct & 1;
                int reg = (khalf << 1) | rbit;
                uint32_t base = (uint32_t)((rb * 8 + kb) * 128 + reg);
#pragma unroll
                for (int j = 0; j < 4; j++) {
                    unsigned short h0, l0, h1, l1;
                    split_bf16(f[2 * j], h0, l0);
                    split_bf16(f[2 * j + 1], h1, l1);
                    uint32_t off = base + (uint32_t)(lane_row * 4 + j) * 4;
                    Ah[off] = (uint32_t)h0 | ((uint32_t)h1 << 16);
                    Ah[off + 8192] = (uint32_t)l0 | ((uint32_t)l1 << 16);
                }
            }
            __syncthreads();

            switch (w >> 1) {
                case 0: view_mainloop<1>(Bg, Ah, slab, us, w, lane); break;
                case 1: view_mainloop<2>(Bg, Ah, slab, us, w, lane); break;
                case 2: view_mainloop<3>(Bg, Ah, slab, us, w, lane); break;
                default: view_mainloop<4>(Bg, Ah, slab, us, w, lane); break;
            }
            __syncthreads();

            for (int i = tid; i < TN * KK; i += 256) {
                float s = 0.0f;
#pragma unroll
                for (int ww = 0; ww < 8; ww++) s += slab[ww * 1024 + i];
                mah[i] = s;
            }
            __syncthreads();

            if (tid < TN) {
                int n = n0 + tid;
                if (n < Npts) {
                    float lp[KK];
                    float m = -3.0e38f;
#pragma unroll
                    for (int k = 0; k < KK; k++) {
                        lp[k] = fmaf(-0.5f, mah[tid * KK + k],
                                     g_logc[v * KK + k]);
                        m = fmaxf(m, lp[k]);
                    }
                    float se = 0.0f;
#pragma unroll
                    for (int k = 0; k < KK; k++) se += expf(lp[k] - m);
                    float e = -(m + logf(se));
                    out[(size_t)n * VV + v] = e;
                    if (v == 0) {
                        e_prev = e;
                    } else {
                        float mm = fminf(e_prev, e);
                        float a = expf(mm - e_prev);
                        float b = expf(mm - e);
                        float inv = 1.0f / (a + b);
                        size_t wb = (size_t)2 * Npts;
                        out[wb + (size_t)n * VV] = a * inv;
                        out[wb + (size_t)n * VV + 1] = b * inv;
                        esum += e_prev + e;
                    }
                }
            }
            __syncthreads();
        }
    }

    for (int o = 16; o; o >>= 1) esum += __shfl_xor_sync(0xffffffffu, esum, o);
    if (lane == 0) wsum[w] = esum;
    __syncthreads();
    if (tid < 8) {
        float x = wsum[tid];
        for (int o = 4; o; o >>= 1) x += __shfl_xor_sync(0x000000ffu, x, o);
        if (tid == 0) atomicAdd(&out[(size_t)4 * Npts], x);
    }
}

// ---------------------------------------------------------------------------
extern "C" void kernel_launch(void* const* d_in, const int* in_sizes, int n_in,
                              void* d_out, int out_size) {
    (void)n_in;
    (void)out_size;
    const float* z = (const float*)d_in[0];
    const float* phi = (const float*)d_in[1];
    const float* mu = (const float*)d_in[2];
    const float* sigma = (const float*)d_in[3];
    float* out = (float*)d_out;

    const int Npts = in_sizes[0] / (VV * DD);
    const int ntiles = (Npts + TN - 1) / TN;

    static int nsm = 0;
    if (nsm == 0) {
        int dev = 0;
        cudaGetDevice(&dev);
        cudaDeviceGetAttribute(&nsm, cudaDevAttrMultiProcessorCount, dev);
        if (nsm <= 0) nsm = 148;
    }

    const int SETUP_SMEM =
        (2 * DD * (DD + 1) + 2 * DD + 3 * 32 * 33) * (int)sizeof(float);
    const int MAIN_SMEM = 106496;

    cudaFuncSetAttribute(setup_kernel,
                         cudaFuncAttributeMaxDynamicSharedMemorySize, SETUP_SMEM);
    cudaFuncSetAttribute(main_kernel,
                         cudaFuncAttributeMaxDynamicSharedMemorySize, MAIN_SMEM);

    setup_kernel<<<VV * KK, 256, SETUP_SMEM>>>(phi, mu, sigma, out, Npts);

    int grid = nsm;
    if (grid > ntiles) grid = ntiles;
    main_kernel<<<grid, 256, MAIN_SMEM>>>(z, out, Npts, ntiles);
}

// round 9
// speedup vs baseline: 3.3118x; 1.0348x over previous
#include <cuda_runtime.h>
#include <cuda_bf16.h>
#include <math.h>
#include <stdint.h>

#define VV 2
#define KK 8
#define DD 128
#define TN 128
#define LOG2PI_F 1.8378770664093453f

__device__ uint32_t g_Bfrag[VV * KK * 9216];
__device__ float g_u[VV * KK * DD];
__device__ float g_logc[VV * KK];
__device__ float g_pen[VV * KK];
__device__ int g_ticket;

__device__ __forceinline__ void split_bf16(float x, unsigned short& h, unsigned short& l) {
    __nv_bfloat16 hb = __float2bfloat16(x);
    float r = x - __bfloat162float(hb);
    __nv_bfloat16 lb = __float2bfloat16(r);
    h = __bfloat16_as_ushort(hb);
    l = __bfloat16_as_ushort(lb);
}

#define MMA16816(c, a, b)                                                      \
    asm volatile(                                                              \
        "mma.sync.aligned.m16n8k16.row.col.f32.bf16.bf16.f32 "                 \
        "{%0,%1,%2,%3}, {%4,%5,%6,%7}, {%8,%9}, {%0,%1,%2,%3};"                \
        : "+f"((c)[0]), "+f"((c)[1]), "+f"((c)[2]), "+f"((c)[3])               \
        : "r"((a)[0]), "r"((a)[1]), "r"((a)[2]), "r"((a)[3]),                  \
          "r"((b).x), "r"((b).y))

// ---------------------------------------------------------------------------
// setup (unchanged from R8): Cholesky + blocked triangular inverse
// ---------------------------------------------------------------------------
__global__ void __launch_bounds__(256)
setup_kernel(const float* __restrict__ phi,
             const float* __restrict__ mu,
             const float* __restrict__ sigma,
             float* __restrict__ out, int Npts) {
    extern __shared__ float sm[];
    float (*A)[DD + 1] = (float (*)[DD + 1])sm;
    float (*M)[DD + 1] = (float (*)[DD + 1])(sm + DD * (DD + 1));
    float* red = sm + 2 * DD * (DD + 1);
    float* mus = red + DD;
    float* Tb = mus + DD;

    const int tid = threadIdx.x;
    const int t = tid & 127;
    const int h = tid >> 7;
    const int v = blockIdx.x / KK;
    const int k = blockIdx.x % KK;
    const float* S = sigma + (size_t)(v * KK + k) * DD * DD;

    if (blockIdx.x == 0 && tid == 0) {
        out[(size_t)4 * Npts] = 0.0f;
        g_ticket = 0;
    }

    for (int idx = tid; idx < DD * DD; idx += 256)
        A[idx >> 7][idx & 127] = S[idx];
    __syncthreads();

    if (tid < DD) {
        float dg = A[tid][tid] + 1e-6f;
        A[tid][tid] = dg;
        red[tid] = 1.0f / (dg + 1e-12f);
    }
    __syncthreads();
    for (int s = 64; s > 0; s >>= 1) {
        if (tid < s) red[tid] += red[tid + s];
        __syncthreads();
    }
    if (tid == 0) g_pen[v * KK + k] = red[0];
    __syncthreads();

    for (int j = 0; j < DD; j++) {
        if (tid == j) A[j][j] = sqrtf(A[j][j]);
        __syncthreads();
        if (tid < DD && tid > j) A[tid][j] = A[tid][j] / A[j][j];
        __syncthreads();
        if (t > j) {
            float lij = A[t][j];
#pragma unroll 4
            for (int l = j + 1 + h; l <= t; l += 2)
                A[t][l] = fmaf(-lij, A[l][j], A[t][l]);
        }
        __syncthreads();
    }

    if (tid < DD) red[tid] = logf(A[tid][tid]);
    __syncthreads();
    for (int s = 64; s > 0; s >>= 1) {
        if (tid < s) red[tid] += red[tid + s];
        __syncthreads();
    }
    float logdet = fmaxf(2.0f * red[0], logf(1e-6f));
    __syncthreads();

    for (int idx = tid; idx < DD * DD; idx += 256)
        M[idx >> 7][idx & 127] = 0.0f;
    __syncthreads();

    if (tid < DD) {
        const int q = tid >> 5;
        const int c = tid & 31;
        const int base = q * 32;
        for (int j = c; j < 32; j++) {
            float s = 0.0f;
            for (int i = c; i < j; i++)
                s = fmaf(A[base + j][base + i], M[base + i][base + c], s);
            M[base + j][base + c] =
                (((j == c) ? 1.0f : 0.0f) - s) / A[base + j][base + j];
        }
    }
    __syncthreads();

    {
        const int row = tid >> 3;
        const int c0 = (tid & 7) * 4;
        for (int d = 1; d < 4; d++) {
            const int nb = 4 - d;
            for (int b = 0; b < nb; b++) {
                const int p = b + d, q = b;
                float s0 = 0.0f, s1 = 0.0f, s2 = 0.0f, s3 = 0.0f;
                for (int r = q; r < p; r++) {
#pragma unroll 8
                    for (int i = 0; i < 32; i++) {
                        float a = A[p * 32 + row][r * 32 + i];
                        const float* mr = &M[r * 32 + i][q * 32 + c0];
                        s0 = fmaf(a, mr[0], s0);
                        s1 = fmaf(a, mr[1], s1);
                        s2 = fmaf(a, mr[2], s2);
                        s3 = fmaf(a, mr[3], s3);
                    }
                }
                float* tr = &Tb[b * 1056 + row * 33 + c0];
                tr[0] = s0; tr[1] = s1; tr[2] = s2; tr[3] = s3;
            }
            __syncthreads();
            for (int b = 0; b < nb; b++) {
                const int p = b + d, q = b;
                float s0 = 0.0f, s1 = 0.0f, s2 = 0.0f, s3 = 0.0f;
                for (int i = 0; i <= row; i++) {
                    float a = M[p * 32 + row][p * 32 + i];
                    const float* tr = &Tb[b * 1056 + i * 33 + c0];
                    s0 = fmaf(a, tr[0], s0);
                    s1 = fmaf(a, tr[1], s1);
                    s2 = fmaf(a, tr[2], s2);
                    s3 = fmaf(a, tr[3], s3);
                }
                float* mr = &M[p * 32 + row][q * 32 + c0];
                mr[0] = -s0; mr[1] = -s1; mr[2] = -s2; mr[3] = -s3;
            }
            __syncthreads();
        }
    }

    if (tid < DD) mus[tid] = mu[(size_t)(v * KK + k) * DD + tid];
    __syncthreads();
    if (tid < DD) {
        float u = 0.0f;
        for (int j = 0; j < DD; j++) u = fmaf(M[tid][j], mus[j], u);
        g_u[(size_t)(v * KK + k) * DD + tid] = u;
    }

    uint32_t* blob = g_Bfrag + (size_t)(v * KK + k) * 9216;
    for (int idx = tid; idx < 9216; idx += 256) {
        int reg = idx & 1;
        int lane = (idx >> 1) & 31;
        int hl = (idx >> 6) & 1;
        int ws = idx >> 7;
        int w = ws / 9;
        int s = ws - w * 9;
        int nA = (w >> 1) + 1;
        int b = (s < nA) ? w : 15 - w;
        int kb = (s < nA) ? s : s - nA;
        int col = b * 8 + (lane >> 2);
        int k0 = kb * 16 + (lane & 3) * 2 + reg * 8;
        unsigned short h0, l0, h1, l1;
        split_bf16(M[col][k0], h0, l0);
        split_bf16(M[col][k0 + 1], h1, l1);
        blob[idx] = hl ? ((uint32_t)l0 | ((uint32_t)l1 << 16))
                       : ((uint32_t)h0 | ((uint32_t)h1 << 16));
    }

    if (tid == 0) {
        float pm = -3.0e38f;
        for (int i = 0; i < KK; i++) pm = fmaxf(pm, phi[v * KK + i]);
        float se = 0.0f;
        for (int i = 0; i < KK; i++) se += expf(phi[v * KK + i] - pm);
        float logpi = phi[v * KK + k] - pm - logf(se);
        g_logc[v * KK + k] = logpi - 0.5f * (float)DD * LOG2PI_F - 0.5f * logdet;
    }
}

// ---------------------------------------------------------------------------
// mainloop: rb processed in 2 chunks of 4 (acc halved -> <=128 regs)
// ---------------------------------------------------------------------------
template <int NA>
__device__ __forceinline__ void view_mainloop(
    const uint32_t* __restrict__ Bg, const uint32_t* __restrict__ Ah,
    float* __restrict__ slab, const float* __restrict__ us,
    int w, int lane) {
    constexpr int NB = 9 - NA;
    const int tq = lane & 3;
    const int tr = lane >> 2;

    uint2 BfA[NA][2], BfB[NB][2];
    {
        const uint32_t* bc = Bg + w * 9 * 128 + lane * 2;
#pragma unroll
        for (int s = 0; s < NA; s++) {
            BfA[s][0] = *(const uint2*)(bc + (s * 2 + 0) * 64);
            BfA[s][1] = *(const uint2*)(bc + (s * 2 + 1) * 64);
        }
#pragma unroll
        for (int s = 0; s < NB; s++) {
            BfB[s][0] = *(const uint2*)(bc + ((NA + s) * 2 + 0) * 64);
            BfB[s][1] = *(const uint2*)(bc + ((NA + s) * 2 + 1) * 64);
        }
    }

    for (int comp = 0; comp < KK; comp++) {
        const float* uc = us + comp * DD;
        const float uA0 = uc[w * 8 + tq * 2];
        const float uA1 = uc[w * 8 + tq * 2 + 1];
        const float uB0 = uc[(15 - w) * 8 + tq * 2];
        const float uB1 = uc[(15 - w) * 8 + tq * 2 + 1];

#pragma unroll
        for (int rbc = 0; rbc < 2; rbc++) {
            float accA[4][4], accB[4][4];
#pragma unroll
            for (int r4 = 0; r4 < 4; r4++)
#pragma unroll
                for (int r = 0; r < 4; r++) {
                    accA[r4][r] = 0.0f;
                    accB[r4][r] = 0.0f;
                }

#pragma unroll
            for (int kb = 0; kb < NB; kb++) {
                uint32_t a[4][4], al[4][4];
#pragma unroll
                for (int r4 = 0; r4 < 4; r4++) {
                    const uint32_t* ap =
                        Ah + ((rbc * 4 + r4) * 8 + kb) * 128 + lane * 4;
                    uint4 av = *(const uint4*)ap;
                    uint4 lv = *(const uint4*)(ap + 8192);
                    a[r4][0] = av.x; a[r4][1] = av.y;
                    a[r4][2] = av.z; a[r4][3] = av.w;
                    al[r4][0] = lv.x; al[r4][1] = lv.y;
                    al[r4][2] = lv.z; al[r4][3] = lv.w;
                }
#pragma unroll
                for (int r4 = 0; r4 < 4; r4++)
                    MMA16816(accB[r4], a[r4], BfB[kb][0]);
                if (kb < NA) {
#pragma unroll
                    for (int r4 = 0; r4 < 4; r4++)
                        MMA16816(accA[r4], a[r4], BfA[kb][0]);
                }
#pragma unroll
                for (int r4 = 0; r4 < 4; r4++)
                    MMA16816(accB[r4], a[r4], BfB[kb][1]);
                if (kb < NA) {
#pragma unroll
                    for (int r4 = 0; r4 < 4; r4++)
                        MMA16816(accA[r4], a[r4], BfA[kb][1]);
                }
#pragma unroll
                for (int r4 = 0; r4 < 4; r4++)
                    MMA16816(accB[r4], al[r4], BfB[kb][0]);
                if (kb < NA) {
#pragma unroll
                    for (int r4 = 0; r4 < 4; r4++)
                        MMA16816(accA[r4], al[r4], BfA[kb][0]);
                }
            }

            // epilogue for this rb-chunk
#pragma unroll
            for (int r4 = 0; r4 < 4; r4++) {
                const int rb = rbc * 4 + r4;
                float d0 = accA[r4][0] - uA0;
                float d1 = accA[r4][1] - uA1;
                float d2 = accB[r4][0] - uB0;
                float d3 = accB[r4][1] - uB1;
                float s0 = d0 * d0 + d1 * d1 + d2 * d2 + d3 * d3;
                float e0 = accA[r4][2] - uA0;
                float e1 = accA[r4][3] - uA1;
                float e2 = accB[r4][2] - uB0;
                float e3 = accB[r4][3] - uB1;
                float s1 = e0 * e0 + e1 * e1 + e2 * e2 + e3 * e3;
                s0 += __shfl_xor_sync(0xffffffffu, s0, 1);
                s0 += __shfl_xor_sync(0xffffffffu, s0, 2);
                s1 += __shfl_xor_sync(0xffffffffu, s1, 1);
                s1 += __shfl_xor_sync(0xffffffffu, s1, 2);
                if (tq == 0) {
                    slab[w * 1024 + (rb * 16 + tr) * 8 + comp] = s0;
                    slab[w * 1024 + (rb * 16 + tr + 8) * 8 + comp] = s1;
                }
            }
        }

        // prefetch next comp's B fragments
        if (comp + 1 < KK) {
            const uint32_t* bc =
                Bg + (size_t)(comp + 1) * 9216 + w * 9 * 128 + lane * 2;
#pragma unroll
            for (int s = 0; s < NA; s++) {
                BfA[s][0] = *(const uint2*)(bc + (s * 2 + 0) * 64);
                BfA[s][1] = *(const uint2*)(bc + (s * 2 + 1) * 64);
            }
#pragma unroll
            for (int s = 0; s < NB; s++) {
                BfB[s][0] = *(const uint2*)(bc + ((NA + s) * 2 + 0) * 64);
                BfB[s][1] = *(const uint2*)(bc + ((NA + s) * 2 + 1) * 64);
            }
        }
    }
}

// ---------------------------------------------------------------------------
// main: persistent, atomic ticket, views fused; 2 CTAs/SM target.
// ---------------------------------------------------------------------------
__global__ void __launch_bounds__(256, 2)
main_kernel(const float* __restrict__ z, float* __restrict__ out,
            int Npts, int ntiles) {
    extern __shared__ __align__(16) unsigned char smraw[];
    uint32_t* Ah = (uint32_t*)smraw;
    float* slab = (float*)(smraw + 65536);
    float* us = (float*)(smraw + 98304);
    float* mah = (float*)(smraw + 102400);
    __shared__ int s_tile;
    __shared__ float wsum[8];

    const int tid = threadIdx.x;
    const int w = tid >> 5;
    const int lane = tid & 31;

    if (blockIdx.x == 0 && tid == 0) {
        float p = 0.0f;
#pragma unroll
        for (int i = 0; i < VV * KK; i++) p += g_pen[i];
        out[(size_t)4 * Npts + 1] = p;
    }

    float esum = 0.0f;

    for (;;) {
        if (tid == 0) s_tile = atomicAdd(&g_ticket, 1);
        __syncthreads();
        const int tile = s_tile;
        if (tile >= ntiles) break;
        const int n0 = tile * TN;

        float e_prev = 0.0f;

        for (int v = 0; v < VV; v++) {
            const uint32_t* Bg = g_Bfrag + (size_t)v * KK * 9216;

            for (int i = tid; i < KK * DD; i += 256)
                us[i] = g_u[(size_t)v * KK * DD + i];

            const float* zr = z + (size_t)v * Npts * DD;
#pragma unroll
            for (int it = 0; it < 8; it++) {
                int idx = tid + it * 256;
                int p = idx >> 4;
                int oct = idx & 15;
                int n = n0 + p;
                float f[8];
                if (n < Npts) {
                    const float4* src =
                        (const float4*)(zr + (size_t)n * DD + oct * 8);
                    float4 a = src[0], b = src[1];
                    f[0] = a.x; f[1] = a.y; f[2] = a.z; f[3] = a.w;
                    f[4] = b.x; f[5] = b.y; f[6] = b.z; f[7] = b.w;
                } else {
#pragma unroll
                    for (int j = 0; j < 8; j++) f[j] = 0.0f;
                }
                int rb = p >> 4;
                int row_in = p & 15;
                int lane_row = row_in & 7;
                int rbit = row_in >> 3;
                int kb = oct >> 1;
                int khalf = oct & 1;
                int reg = (khalf << 1) | rbit;
                uint32_t base = (uint32_t)((rb * 8 + kb) * 128 + reg);
#pragma unroll
                for (int j = 0; j < 4; j++) {
                    unsigned short h0, l0, h1, l1;
                    split_bf16(f[2 * j], h0, l0);
                    split_bf16(f[2 * j + 1], h1, l1);
                    uint32_t off = base + (uint32_t)(lane_row * 4 + j) * 4;
                    Ah[off] = (uint32_t)h0 | ((uint32_t)h1 << 16);
                    Ah[off + 8192] = (uint32_t)l0 | ((uint32_t)l1 << 16);
                }
            }
            __syncthreads();

            switch (w >> 1) {
                case 0: view_mainloop<1>(Bg, Ah, slab, us, w, lane); break;
                case 1: view_mainloop<2>(Bg, Ah, slab, us, w, lane); break;
                case 2: view_mainloop<3>(Bg, Ah, slab, us, w, lane); break;
                default: view_mainloop<4>(Bg, Ah, slab, us, w, lane); break;
            }
            __syncthreads();

            for (int i = tid; i < TN * KK; i += 256) {
                float s = 0.0f;
#pragma unroll
                for (int ww = 0; ww < 8; ww++) s += slab[ww * 1024 + i];
                mah[i] = s;
            }
            __syncthreads();

            if (tid < TN) {
                int n = n0 + tid;
                if (n < Npts) {
                    float lp[KK];
                    float m = -3.0e38f;
#pragma unroll
                    for (int k = 0; k < KK; k++) {
                        lp[k] = fmaf(-0.5f, mah[tid * KK + k],
                                     g_logc[v * KK + k]);
                        m = fmaxf(m, lp[k]);
                    }
                    float se = 0.0f;
#pragma unroll
                    for (int k = 0; k < KK; k++) se += expf(lp[k] - m);
                    float e = -(m + logf(se));
                    out[(size_t)n * VV + v] = e;
                    if (v == 0) {
                        e_prev = e;
                    } else {
                        float mm = fminf(e_prev, e);
                        float a = expf(mm - e_prev);
                        float b = expf(mm - e);
                        float inv = 1.0f / (a + b);
                        size_t wb = (size_t)2 * Npts;
                        out[wb + (size_t)n * VV] = a * inv;
                        out[wb + (size_t)n * VV + 1] = b * inv;
                        esum += e_prev + e;
                    }
                }
            }
            __syncthreads();
        }
    }

    for (int o = 16; o; o >>= 1) esum += __shfl_xor_sync(0xffffffffu, esum, o);
    if (lane == 0) wsum[w] = esum;
    __syncthreads();
    if (tid < 8) {
        float x = wsum[tid];
        for (int o = 4; o; o >>= 1) x += __shfl_xor_sync(0x000000ffu, x, o);
        if (tid == 0) atomicAdd(&out[(size_t)4 * Npts], x);
    }
}

// ---------------------------------------------------------------------------
extern "C" void kernel_launch(void* const* d_in, const int* in_sizes, int n_in,
                              void* d_out, int out_size) {
    (void)n_in;
    (void)out_size;
    const float* z = (const float*)d_in[0];
    const float* phi = (const float*)d_in[1];
    const float* mu = (const float*)d_in[2];
    const float* sigma = (const float*)d_in[3];
    float* out = (float*)d_out;

    const int Npts = in_sizes[0] / (VV * DD);
    const int ntiles = (Npts + TN - 1) / TN;

    static int nsm = 0;
    if (nsm == 0) {
        int dev = 0;
        cudaGetDevice(&dev);
        cudaDeviceGetAttribute(&nsm, cudaDevAttrMultiProcessorCount, dev);
        if (nsm <= 0) nsm = 148;
    }

    const int SETUP_SMEM =
        (2 * DD * (DD + 1) + 2 * DD + 3 * 32 * 33) * (int)sizeof(float);
    const int MAIN_SMEM = 106496;

    cudaFuncSetAttribute(setup_kernel,
                         cudaFuncAttributeMaxDynamicSharedMemorySize, SETUP_SMEM);
    cudaFuncSetAttribute(main_kernel,
                         cudaFuncAttributeMaxDynamicSharedMemorySize, MAIN_SMEM);

    setup_kernel<<<VV * KK, 256, SETUP_SMEM>>>(phi, mu, sigma, out, Npts);

    int grid = 2 * nsm;
    if (grid > ntiles) grid = ntiles;
    main_kernel<<<grid, 256, MAIN_SMEM>>>(z, out, Npts, ntiles);
}

// round 10
// speedup vs baseline: 3.5410x; 1.0692x over previous
#include <cuda_runtime.h>
#include <cuda_bf16.h>
#include <math.h>
#include <stdint.h>

#define VV 2
#define KK 8
#define DD 128
#define TN 128
#define AST 132   // padded smem row stride (16B-aligned rows)
#define LOG2PI_F 1.8378770664093453f

__device__ uint32_t g_Bfrag[VV * KK * 9216];
__device__ float g_u[VV * KK * DD];
__device__ float g_logc[VV * KK];
__device__ float g_pen[VV * KK];
__device__ int g_ticket;

__device__ __forceinline__ void split_bf16(float x, unsigned short& h, unsigned short& l) {
    __nv_bfloat16 hb = __float2bfloat16(x);
    float r = x - __bfloat162float(hb);
    __nv_bfloat16 lb = __float2bfloat16(r);
    h = __bfloat16_as_ushort(hb);
    l = __bfloat16_as_ushort(lb);
}

#define MMA16816(c, a, b)                                                      \
    asm volatile(                                                              \
        "mma.sync.aligned.m16n8k16.row.col.f32.bf16.bf16.f32 "                 \
        "{%0,%1,%2,%3}, {%4,%5,%6,%7}, {%8,%9}, {%0,%1,%2,%3};"                \
        : "+f"((c)[0]), "+f"((c)[1]), "+f"((c)[2]), "+f"((c)[3])               \
        : "r"((a)[0]), "r"((a)[1]), "r"((a)[2]), "r"((a)[3]),                  \
          "r"((b).x), "r"((b).y))

// ---------------------------------------------------------------------------
// setup: LDL^T factorization (1 barrier/j, float4 update, no sqrt/div chains)
// + blocked unit-triangular inverse; M = D^{-1/2} Lu^{-1} folded into blobs.
// ---------------------------------------------------------------------------
__global__ void __launch_bounds__(256)
setup_kernel(const float* __restrict__ phi,
             const float* __restrict__ mu,
             const float* __restrict__ sigma,
             float* __restrict__ out, int Npts) {
    extern __shared__ float sm[];
    float (*A)[AST] = (float (*)[AST])sm;
    float (*M)[AST] = (float (*)[AST])(sm + DD * AST);
    float* red = sm + 2 * DD * AST;     // 128
    float* dinv = red + DD;             // 128
    float* scl = dinv + DD;             // 128
    float* mus = scl + DD;              // 128
    float* Tb = mus + DD;               // 3*32*33

    const int tid = threadIdx.x;
    const int t = tid & 127;
    const int h = tid >> 7;
    const int v = blockIdx.x / KK;
    const int k = blockIdx.x % KK;
    const float* S = sigma + (size_t)(v * KK + k) * DD * DD;

    if (blockIdx.x == 0 && tid == 0) {
        out[(size_t)4 * Npts] = 0.0f;
        g_ticket = 0;
    }

    for (int idx = tid; idx < DD * DD; idx += 256)
        A[idx >> 7][idx & 127] = S[idx];
    __syncthreads();

    if (tid < DD) {
        float dg = A[tid][tid] + 1e-6f;
        A[tid][tid] = dg;
        red[tid] = 1.0f / (dg + 1e-12f);
    }
    __syncthreads();
    for (int s = 64; s > 0; s >>= 1) {
        if (tid < s) red[tid] += red[tid + s];
        __syncthreads();
    }
    if (tid == 0) g_pen[v * KK + k] = red[0];
    __syncthreads();

    // LDL^T: raw columns, 1 barrier per j, float4-vectorized trailing update
    for (int j = 0; j < DD; j++) {
        float invd = __fdividef(1.0f, A[j][j]);
        int n = t - j;                    // cols l in (j, t]
        if (n > 0) {
            float mf = -A[t][j] * invd;
            int half = (n + 1) >> 1;
            int lo = j + 1 + h * half;
            int hi = (h == 0) ? (j + half) : t;   // inclusive
            int l = lo;
            for (; l <= hi && (l & 3); l++)
                A[t][l] = fmaf(mf, A[l][j], A[t][l]);
            for (; l + 3 <= hi; l += 4) {
                float4 av = *(float4*)&A[t][l];
                av.x = fmaf(mf, A[l][j], av.x);
                av.y = fmaf(mf, A[l + 1][j], av.y);
                av.z = fmaf(mf, A[l + 2][j], av.z);
                av.w = fmaf(mf, A[l + 3][j], av.w);
                *(float4*)&A[t][l] = av;
            }
            for (; l <= hi; l++)
                A[t][l] = fmaf(mf, A[l][j], A[t][l]);
        }
        __syncthreads();
    }

    // d_j = A[j][j] (row/col j untouched after step j)
    if (tid < DD) {
        float d = A[tid][tid];
        red[tid] = logf(d);
        dinv[tid] = __fdividef(1.0f, d);
        scl[tid] = rsqrtf(d);
    }
    __syncthreads();
    for (int s = 64; s > 0; s >>= 1) {
        if (tid < s) red[tid] += red[tid + s];
        __syncthreads();
    }
    float logdet = fmaxf(red[0], logf(1e-6f));
    __syncthreads();

    // ---- blocked inverse of UNIT lower Lu (Lu[t][j] = A[t][j]*dinv[j]) ----
    for (int idx = tid; idx < DD * DD; idx += 256)
        M[idx >> 7][idx & 127] = 0.0f;
    __syncthreads();

    // Phase B: invert 4 diagonal 32x32 unit-lower blocks (no divisions)
    if (tid < DD) {
        const int q = tid >> 5;
        const int c = tid & 31;
        const int base = q * 32;
        M[base + c][base + c] = 1.0f;
        for (int j = c + 1; j < 32; j++) {
            float s = 0.0f;
            for (int i = c; i < j; i++)
                s = fmaf(A[base + j][base + i] * dinv[base + i],
                         M[base + i][base + c], s);
            M[base + j][base + c] = -s;
        }
    }
    __syncthreads();

    // Phase C: off-diagonal waves d=1..3:  M_pq = -M_pp * (sum_r Lu_pr M_rq)
    {
        const int row = tid >> 3;
        const int c0 = (tid & 7) * 4;
        for (int d = 1; d < 4; d++) {
            const int nb = 4 - d;
            for (int b = 0; b < nb; b++) {
                const int p = b + d, q = b;
                float s0 = 0.0f, s1 = 0.0f, s2 = 0.0f, s3 = 0.0f;
                for (int r = q; r < p; r++) {
#pragma unroll 8
                    for (int i = 0; i < 32; i++) {
                        float a = A[p * 32 + row][r * 32 + i] * dinv[r * 32 + i];
                        const float* mr = &M[r * 32 + i][q * 32 + c0];
                        s0 = fmaf(a, mr[0], s0);
                        s1 = fmaf(a, mr[1], s1);
                        s2 = fmaf(a, mr[2], s2);
                        s3 = fmaf(a, mr[3], s3);
                    }
                }
                float* tr = &Tb[b * 1056 + row * 33 + c0];
                tr[0] = s0; tr[1] = s1; tr[2] = s2; tr[3] = s3;
            }
            __syncthreads();
            for (int b = 0; b < nb; b++) {
                const int p = b + d, q = b;
                float s0 = 0.0f, s1 = 0.0f, s2 = 0.0f, s3 = 0.0f;
                for (int i = 0; i <= row; i++) {
                    float a = M[p * 32 + row][p * 32 + i];
                    const float* tr = &Tb[b * 1056 + i * 33 + c0];
                    s0 = fmaf(a, tr[0], s0);
                    s1 = fmaf(a, tr[1], s1);
                    s2 = fmaf(a, tr[2], s2);
                    s3 = fmaf(a, tr[3], s3);
                }
                float* mr = &M[p * 32 + row][q * 32 + c0];
                mr[0] = -s0; mr[1] = -s1; mr[2] = -s2; mr[3] = -s3;
            }
            __syncthreads();
        }
    }

    if (tid < DD) mus[tid] = mu[(size_t)(v * KK + k) * DD + tid];
    __syncthreads();
    if (tid < DD) {
        float u = 0.0f;
        const float4* mr = (const float4*)&M[tid][0];
        const float4* mv = (const float4*)mus;
        for (int j = 0; j < DD / 4; j++) {
            float4 a = mr[j], b = mv[j];
            u = fmaf(a.x, b.x, u);
            u = fmaf(a.y, b.y, u);
            u = fmaf(a.z, b.z, u);
            u = fmaf(a.w, b.w, u);
        }
        g_u[(size_t)(v * KK + k) * DD + tid] = u * scl[tid];
    }

    uint32_t* blob = g_Bfrag + (size_t)(v * KK + k) * 9216;
    for (int idx = tid; idx < 9216; idx += 256) {
        int reg = idx & 1;
        int lane = (idx >> 1) & 31;
        int hl = (idx >> 6) & 1;
        int ws = idx >> 7;
        int w = ws / 9;
        int s = ws - w * 9;
        int nA = (w >> 1) + 1;
        int b = (s < nA) ? w : 15 - w;
        int kb = (s < nA) ? s : s - nA;
        int col = b * 8 + (lane >> 2);
        int k0 = kb * 16 + (lane & 3) * 2 + reg * 8;
        float sc = scl[col];
        unsigned short h0, l0, h1, l1;
        split_bf16(M[col][k0] * sc, h0, l0);
        split_bf16(M[col][k0 + 1] * sc, h1, l1);
        blob[idx] = hl ? ((uint32_t)l0 | ((uint32_t)l1 << 16))
                       : ((uint32_t)h0 | ((uint32_t)h1 << 16));
    }

    if (tid == 0) {
        float pm = -3.0e38f;
        for (int i = 0; i < KK; i++) pm = fmaxf(pm, phi[v * KK + i]);
        float se = 0.0f;
        for (int i = 0; i < KK; i++) se += expf(phi[v * KK + i] - pm);
        float logpi = phi[v * KK + k] - pm - logf(se);
        g_logc[v * KK + k] = logpi - 0.5f * (float)DD * LOG2PI_F - 0.5f * logdet;
    }
}

// ---------------------------------------------------------------------------
// mainloop (unchanged from R9): rb in 2 chunks of 4, <=128 regs
// ---------------------------------------------------------------------------
template <int NA>
__device__ __forceinline__ void view_mainloop(
    const uint32_t* __restrict__ Bg, const uint32_t* __restrict__ Ah,
    float* __restrict__ slab, const float* __restrict__ us,
    int w, int lane) {
    constexpr int NB = 9 - NA;
    const int tq = lane & 3;
    const int tr = lane >> 2;

    uint2 BfA[NA][2], BfB[NB][2];
    {
        const uint32_t* bc = Bg + w * 9 * 128 + lane * 2;
#pragma unroll
        for (int s = 0; s < NA; s++) {
            BfA[s][0] = *(const uint2*)(bc + (s * 2 + 0) * 64);
            BfA[s][1] = *(const uint2*)(bc + (s * 2 + 1) * 64);
        }
#pragma unroll
        for (int s = 0; s < NB; s++) {
            BfB[s][0] = *(const uint2*)(bc + ((NA + s) * 2 + 0) * 64);
            BfB[s][1] = *(const uint2*)(bc + ((NA + s) * 2 + 1) * 64);
        }
    }

    for (int comp = 0; comp < KK; comp++) {
        const float* uc = us + comp * DD;
        const float uA0 = uc[w * 8 + tq * 2];
        const float uA1 = uc[w * 8 + tq * 2 + 1];
        const float uB0 = uc[(15 - w) * 8 + tq * 2];
        const float uB1 = uc[(15 - w) * 8 + tq * 2 + 1];

#pragma unroll
        for (int rbc = 0; rbc < 2; rbc++) {
            float accA[4][4], accB[4][4];
#pragma unroll
            for (int r4 = 0; r4 < 4; r4++)
#pragma unroll
                for (int r = 0; r < 4; r++) {
                    accA[r4][r] = 0.0f;
                    accB[r4][r] = 0.0f;
                }

#pragma unroll
            for (int kb = 0; kb < NB; kb++) {
                uint32_t a[4][4], al[4][4];
#pragma unroll
                for (int r4 = 0; r4 < 4; r4++) {
                    const uint32_t* ap =
                        Ah + ((rbc * 4 + r4) * 8 + kb) * 128 + lane * 4;
                    uint4 av = *(const uint4*)ap;
                    uint4 lv = *(const uint4*)(ap + 8192);
                    a[r4][0] = av.x; a[r4][1] = av.y;
                    a[r4][2] = av.z; a[r4][3] = av.w;
                    al[r4][0] = lv.x; al[r4][1] = lv.y;
                    al[r4][2] = lv.z; al[r4][3] = lv.w;
                }
#pragma unroll
                for (int r4 = 0; r4 < 4; r4++)
                    MMA16816(accB[r4], a[r4], BfB[kb][0]);
                if (kb < NA) {
#pragma unroll
                    for (int r4 = 0; r4 < 4; r4++)
                        MMA16816(accA[r4], a[r4], BfA[kb][0]);
                }
#pragma unroll
                for (int r4 = 0; r4 < 4; r4++)
                    MMA16816(accB[r4], a[r4], BfB[kb][1]);
                if (kb < NA) {
#pragma unroll
                    for (int r4 = 0; r4 < 4; r4++)
                        MMA16816(accA[r4], a[r4], BfA[kb][1]);
                }
#pragma unroll
                for (int r4 = 0; r4 < 4; r4++)
                    MMA16816(accB[r4], al[r4], BfB[kb][0]);
                if (kb < NA) {
#pragma unroll
                    for (int r4 = 0; r4 < 4; r4++)
                        MMA16816(accA[r4], al[r4], BfA[kb][0]);
                }
            }

#pragma unroll
            for (int r4 = 0; r4 < 4; r4++) {
                const int rb = rbc * 4 + r4;
                float d0 = accA[r4][0] - uA0;
                float d1 = accA[r4][1] - uA1;
                float d2 = accB[r4][0] - uB0;
                float d3 = accB[r4][1] - uB1;
                float s0 = d0 * d0 + d1 * d1 + d2 * d2 + d3 * d3;
                float e0 = accA[r4][2] - uA0;
                float e1 = accA[r4][3] - uA1;
                float e2 = accB[r4][2] - uB0;
                float e3 = accB[r4][3] - uB1;
                float s1 = e0 * e0 + e1 * e1 + e2 * e2 + e3 * e3;
                s0 += __shfl_xor_sync(0xffffffffu, s0, 1);
                s0 += __shfl_xor_sync(0xffffffffu, s0, 2);
                s1 += __shfl_xor_sync(0xffffffffu, s1, 1);
                s1 += __shfl_xor_sync(0xffffffffu, s1, 2);
                if (tq == 0) {
                    slab[w * 1024 + (rb * 16 + tr) * 8 + comp] = s0;
                    slab[w * 1024 + (rb * 16 + tr + 8) * 8 + comp] = s1;
                }
            }
        }

        if (comp + 1 < KK) {
            const uint32_t* bc =
                Bg + (size_t)(comp + 1) * 9216 + w * 9 * 128 + lane * 2;
#pragma unroll
            for (int s = 0; s < NA; s++) {
                BfA[s][0] = *(const uint2*)(bc + (s * 2 + 0) * 64);
                BfA[s][1] = *(const uint2*)(bc + (s * 2 + 1) * 64);
            }
#pragma unroll
            for (int s = 0; s < NB; s++) {
                BfB[s][0] = *(const uint2*)(bc + ((NA + s) * 2 + 0) * 64);
                BfB[s][1] = *(const uint2*)(bc + ((NA + s) * 2 + 1) * 64);
            }
        }
    }
}

// ---------------------------------------------------------------------------
// main: persistent, atomic ticket, views fused (unchanged from R9)
// ---------------------------------------------------------------------------
__global__ void __launch_bounds__(256, 2)
main_kernel(const float* __restrict__ z, float* __restrict__ out,
            int Npts, int ntiles) {
    extern __shared__ __align__(16) unsigned char smraw[];
    uint32_t* Ah = (uint32_t*)smraw;
    float* slab = (float*)(smraw + 65536);
    float* us = (float*)(smraw + 98304);
    float* mah = (float*)(smraw + 102400);
    __shared__ int s_tile;
    __shared__ float wsum[8];

    const int tid = threadIdx.x;
    const int w = tid >> 5;
    const int lane = tid & 31;

    if (blockIdx.x == 0 && tid == 0) {
        float p = 0.0f;
#pragma unroll
        for (int i = 0; i < VV * KK; i++) p += g_pen[i];
        out[(size_t)4 * Npts + 1] = p;
    }

    float esum = 0.0f;

    for (;;) {
        if (tid == 0) s_tile = atomicAdd(&g_ticket, 1);
        __syncthreads();
        const int tile = s_tile;
        if (tile >= ntiles) break;
        const int n0 = tile * TN;

        float e_prev = 0.0f;

        for (int v = 0; v < VV; v++) {
            const uint32_t* Bg = g_Bfrag + (size_t)v * KK * 9216;

            for (int i = tid; i < KK * DD; i += 256)
                us[i] = g_u[(size_t)v * KK * DD + i];

            const float* zr = z + (size_t)v * Npts * DD;
#pragma unroll
            for (int it = 0; it < 8; it++) {
                int idx = tid + it * 256;
                int p = idx >> 4;
                int oct = idx & 15;
                int n = n0 + p;
                float f[8];
                if (n < Npts) {
                    const float4* src =
                        (const float4*)(zr + (size_t)n * DD + oct * 8);
                    float4 a = src[0], b = src[1];
                    f[0] = a.x; f[1] = a.y; f[2] = a.z; f[3] = a.w;
                    f[4] = b.x; f[5] = b.y; f[6] = b.z; f[7] = b.w;
                } else {
#pragma unroll
                    for (int j = 0; j < 8; j++) f[j] = 0.0f;
                }
                int rb = p >> 4;
                int row_in = p & 15;
                int lane_row = row_in & 7;
                int rbit = row_in >> 3;
                int kb = oct >> 1;
                int khalf = oct & 1;
                int reg = (khalf << 1) | rbit;
                uint32_t base = (uint32_t)((rb * 8 + kb) * 128 + reg);
#pragma unroll
                for (int j = 0; j < 4; j++) {
                    unsigned short h0, l0, h1, l1;
                    split_bf16(f[2 * j], h0, l0);
                    split_bf16(f[2 * j + 1], h1, l1);
                    uint32_t off = base + (uint32_t)(lane_row * 4 + j) * 4;
                    Ah[off] = (uint32_t)h0 | ((uint32_t)h1 << 16);
                    Ah[off + 8192] = (uint32_t)l0 | ((uint32_t)l1 << 16);
                }
            }
            __syncthreads();

            switch (w >> 1) {
                case 0: view_mainloop<1>(Bg, Ah, slab, us, w, lane); break;
                case 1: view_mainloop<2>(Bg, Ah, slab, us, w, lane); break;
                case 2: view_mainloop<3>(Bg, Ah, slab, us, w, lane); break;
                default: view_mainloop<4>(Bg, Ah, slab, us, w, lane); break;
            }
            __syncthreads();

            for (int i = tid; i < TN * KK; i += 256) {
                float s = 0.0f;
#pragma unroll
                for (int ww = 0; ww < 8; ww++) s += slab[ww * 1024 + i];
                mah[i] = s;
            }
            __syncthreads();

            if (tid < TN) {
                int n = n0 + tid;
                if (n < Npts) {
                    float lp[KK];
                    float m = -3.0e38f;
#pragma unroll
                    for (int k = 0; k < KK; k++) {
                        lp[k] = fmaf(-0.5f, mah[tid * KK + k],
                                     g_logc[v * KK + k]);
                        m = fmaxf(m, lp[k]);
                    }
                    float se = 0.0f;
#pragma unroll
                    for (int k = 0; k < KK; k++) se += expf(lp[k] - m);
                    float e = -(m + logf(se));
                    out[(size_t)n * VV + v] = e;
                    if (v == 0) {
                        e_prev = e;
                    } else {
                        float mm = fminf(e_prev, e);
                        float a = expf(mm - e_prev);
                        float b = expf(mm - e);
                        float inv = 1.0f / (a + b);
                        size_t wb = (size_t)2 * Npts;
                        out[wb + (size_t)n * VV] = a * inv;
                        out[wb + (size_t)n * VV + 1] = b * inv;
                        esum += e_prev + e;
                    }
                }
            }
            __syncthreads();
        }
    }

    for (int o = 16; o; o >>= 1) esum += __shfl_xor_sync(0xffffffffu, esum, o);
    if (lane == 0) wsum[w] = esum;
    __syncthreads();
    if (tid < 8) {
        float x = wsum[tid];
        for (int o = 4; o; o >>= 1) x += __shfl_xor_sync(0x000000ffu, x, o);
        if (tid == 0) atomicAdd(&out[(size_t)4 * Npts], x);
    }
}

// ---------------------------------------------------------------------------
extern "C" void kernel_launch(void* const* d_in, const int* in_sizes, int n_in,
                              void* d_out, int out_size) {
    (void)n_in;
    (void)out_size;
    const float* z = (const float*)d_in[0];
    const float* phi = (const float*)d_in[1];
    const float* mu = (const float*)d_in[2];
    const float* sigma = (const float*)d_in[3];
    float* out = (float*)d_out;

    const int Npts = in_sizes[0] / (VV * DD);
    const int ntiles = (Npts + TN - 1) / TN;

    static int nsm = 0;
    if (nsm == 0) {
        int dev = 0;
        cudaGetDevice(&dev);
        cudaDeviceGetAttribute(&nsm, cudaDevAttrMultiProcessorCount, dev);
        if (nsm <= 0) nsm = 148;
    }

    const int SETUP_SMEM =
        (2 * DD * AST + 4 * DD + 3 * 32 * 33) * (int)sizeof(float);
    const int MAIN_SMEM = 106496;

    cudaFuncSetAttribute(setup_kernel,
                         cudaFuncAttributeMaxDynamicSharedMemorySize, SETUP_SMEM);
    cudaFuncSetAttribute(main_kernel,
                         cudaFuncAttributeMaxDynamicSharedMemorySize, MAIN_SMEM);

    setup_kernel<<<VV * KK, 256, SETUP_SMEM>>>(phi, mu, sigma, out, Npts);

    int grid = 2 * nsm;
    if (grid > ntiles) grid = ntiles;
    main_kernel<<<grid, 256, MAIN_SMEM>>>(z, out, Npts, ntiles);
}